// round 10
// baseline (speedup 1.0000x reference)
#include <cuda_runtime.h>
#include <math.h>
#include <stdint.h>

// ---------------- problem constants ----------------
#define BB 4
#define LL 2048
#define DM 1024
#define DIP 4368          // 2*D_INNER + 2*D_STATE + NHEADS
#define DINNER 2048
#define CONVD 2304        // D_INNER + 2*D_STATE
#define NH 16
#define HP 128            // head dim
#define NS 128            // state dim
#define CS 256            // chunk size
#define NC 8              // chunks per sequence

// ---------------- scratch (device globals; no allocation) ----------------
__device__ float g_zxbcdt[(size_t)BB * LL * DIP];     // in-proj output
__device__ float g_xc[(size_t)BB * LL * CONVD];       // conv+silu output (tf32-rounded)
__device__ float g_dt[(size_t)BB * LL * NH];          // softplus(dt)
__device__ float g_Acs[(size_t)BB * NH * NC * CS];    // per-chunk inclusive cumsum of dA
__device__ float g_CBT[(size_t)BB * NC * CS * CS];    // C @ B^T per (b,chunk)
__device__ float g_states[(size_t)BB * NC * NH * HP * NS];
__device__ float g_prev[(size_t)BB * NC * NH * HP * NS];
__device__ float g_y[(size_t)BB * LL * DINNER];       // pre-out-proj activations (tf32-rounded)
__device__ float g_u_r[(size_t)BB * LL * DM];         // tf32-rounded u
__device__ float g_Win_r[(size_t)DIP * DM];           // tf32-rounded W_in
__device__ float g_Wout_r[(size_t)DM * DINNER];       // tf32-rounded W_out

// ---------------- tf32 helpers ----------------
__device__ __forceinline__ uint32_t f2tf32(float f) {
    uint32_t r;
    asm("cvt.rna.tf32.f32 %0, %1;" : "=r"(r) : "f"(f));
    return r;
}

__device__ __forceinline__ void mma_tf32(float c[4], const uint32_t a[4], const uint32_t b[2]) {
    asm volatile(
        "mma.sync.aligned.m16n8k8.row.col.f32.tf32.tf32.f32 "
        "{%0,%1,%2,%3}, {%4,%5,%6,%7}, {%8,%9}, {%0,%1,%2,%3};"
        : "+f"(c[0]), "+f"(c[1]), "+f"(c[2]), "+f"(c[3])
        : "r"(a[0]), "r"(a[1]), "r"(a[2]), "r"(a[3]), "r"(b[0]), "r"(b[1]));
}

__device__ __forceinline__ void ldsm4(uint32_t& r0, uint32_t& r1, uint32_t& r2, uint32_t& r3,
                                      uint32_t addr) {
    asm volatile("ldmatrix.sync.aligned.m8n8.x4.shared.b16 {%0,%1,%2,%3}, [%4];"
                 : "=r"(r0), "=r"(r1), "=r"(r2), "=r"(r3) : "r"(addr));
}

__device__ __forceinline__ void cp16(uint32_t dst, const float* src, bool ok) {
    int sz = ok ? 16 : 0;
    asm volatile("cp.async.cg.shared.global [%0], [%1], 16, %2;\n"
                 :: "r"(dst), "l"(src), "r"(sz));
}
#define CP_COMMIT() asm volatile("cp.async.commit_group;\n")
#define CP_WAIT1()  asm volatile("cp.async.wait_group 1;\n" ::: "memory")

// ---------------- elementwise tf32 rounding ----------------
__global__ void round_tf32(const float* __restrict__ s, float* __restrict__ d, int n)
{
    int i = (blockIdx.x * 256 + threadIdx.x) * 4;
    if (i >= n) return;
    float4 v = *(const float4*)(s + i);
    float4 o;
    o.x = __uint_as_float(f2tf32(v.x));
    o.y = __uint_as_float(f2tf32(v.y));
    o.z = __uint_as_float(f2tf32(v.z));
    o.w = __uint_as_float(f2tf32(v.w));
    *(float4*)(d + i) = o;
}

// ---------------- tf32 NT GEMM: 256 threads, 8 warps, 256x128 CTA tile ----------------
// (round-9 known-good; only cp.async .ca -> .cg)
#define GSTG 3
#define AST (256 * 20)                   // floats per A stage
#define BST (128 * 20)                   // floats per B stage
#define GB_BASE (GSTG * AST)             // B region offset in floats
__global__ __launch_bounds__(256, 1) void gemm_tf32_nt(
    const float* __restrict__ A, int lda, long long sA,
    const float* __restrict__ B, int ldb, long long sB,
    float* __restrict__ C, int ldc, long long sC,
    int N, int K)
{
    extern __shared__ float sm[];
    const float* Ab = A + (size_t)blockIdx.z * sA;
    const float* Bb = B + (size_t)blockIdx.z * sB;
    float* Cb = C + (size_t)blockIdx.z * sC;
    const int m0 = blockIdx.y * 256, n0 = blockIdx.x * 128;
    const int t = threadIdx.x;
    const int lane = t & 31, w = t >> 5;
    const int wm = (w >> 1) * 64, wn = (w & 1) * 64;

    const bool bldr = (t < 128);
    const bool bok = bldr && ((n0 + t) < N);
    const float* aS = Ab + (size_t)(m0 + t) * lda;
    const float* bS = Bb + (size_t)(bok ? n0 + t : 0) * ldb;
    const uint32_t smBase = (uint32_t)__cvta_generic_to_shared(sm);
    const uint32_t dA = smBase + (t * 20) * 4;
    const uint32_t dB = smBase + (GB_BASE + t * 20) * 4;

    const int rowA = wm + (lane & 15);
    const int colA = (lane >> 4) * 4;
    const int rowB = wn + ((lane >> 4) << 3) + (lane & 7);
    const int colB = ((lane >> 3) & 1) * 4;

    float acc[4][8][4];
    #pragma unroll
    for (int i = 0; i < 4; i++)
        #pragma unroll
        for (int j = 0; j < 8; j++)
            #pragma unroll
            for (int q = 0; q < 4; q++) acc[i][j][q] = 0.f;

    const int nIter = K >> 4;
    #pragma unroll
    for (int s = 0; s < GSTG - 1; s++) {
        const uint32_t offA = s * AST * 4;
        const uint32_t offB = s * BST * 4;
        const int k0 = s << 4;
        cp16(dA + offA,      aS + k0,      true);
        cp16(dA + offA + 16, aS + k0 + 4,  true);
        cp16(dA + offA + 32, aS + k0 + 8,  true);
        cp16(dA + offA + 48, aS + k0 + 12, true);
        if (bldr) {
            cp16(dB + offB,      bS + k0,      bok);
            cp16(dB + offB + 16, bS + k0 + 4,  bok);
            cp16(dB + offB + 32, bS + k0 + 8,  bok);
            cp16(dB + offB + 48, bS + k0 + 12, bok);
        }
        CP_COMMIT();
    }

    for (int it = 0; it < nIter; it++) {
        CP_WAIT1();
        __syncthreads();
        const int pf = it + GSTG - 1;
        if (pf < nIter) {
            const uint32_t offA = (pf % GSTG) * AST * 4;
            const uint32_t offB = (pf % GSTG) * BST * 4;
            const int k0 = pf << 4;
            cp16(dA + offA,      aS + k0,      true);
            cp16(dA + offA + 16, aS + k0 + 4,  true);
            cp16(dA + offA + 32, aS + k0 + 8,  true);
            cp16(dA + offA + 48, aS + k0 + 12, true);
            if (bldr) {
                cp16(dB + offB,      bS + k0,      bok);
                cp16(dB + offB + 16, bS + k0 + 4,  bok);
                cp16(dB + offB + 32, bS + k0 + 8,  bok);
                cp16(dB + offB + 48, bS + k0 + 12, bok);
            }
        }
        CP_COMMIT();

        const uint32_t aOct = smBase + (it % GSTG) * AST * 4 + (rowA * 20 + colA) * 4;
        const uint32_t bOct = smBase + GB_BASE * 4 + (it % GSTG) * BST * 4
                              + (rowB * 20 + colB) * 4;
        #pragma unroll
        for (int kk = 0; kk < 16; kk += 8) {
            uint32_t afr[4][4], bfr[8][2];
            #pragma unroll
            for (int mi = 0; mi < 4; mi++)
                ldsm4(afr[mi][0], afr[mi][1], afr[mi][2], afr[mi][3],
                      aOct + kk * 4 + mi * (16 * 20 * 4));
            #pragma unroll
            for (int j = 0; j < 4; j++)
                ldsm4(bfr[2 * j][0], bfr[2 * j][1], bfr[2 * j + 1][0], bfr[2 * j + 1][1],
                      bOct + kk * 4 + j * (16 * 20 * 4));
            #pragma unroll
            for (int mi = 0; mi < 4; mi++)
                #pragma unroll
                for (int ni = 0; ni < 8; ni++)
                    mma_tf32(acc[mi][ni], afr[mi], bfr[ni]);
        }
    }

    const int g = lane >> 2, tt = lane & 3;
    #pragma unroll
    for (int mi = 0; mi < 4; mi++) {
        #pragma unroll
        for (int ni = 0; ni < 8; ni++) {
            int row = m0 + wm + mi * 16 + g;
            int col = n0 + wn + ni * 8 + 2 * tt;
            if (col < N) {
                *(float2*)(Cb + (size_t)row * ldc + col) =
                    make_float2(acc[mi][ni][0], acc[mi][ni][1]);
                *(float2*)(Cb + (size_t)(row + 8) * ldc + col) =
                    make_float2(acc[mi][ni][2], acc[mi][ni][3]);
            }
        }
    }
}

// ---------------- depthwise conv (K=4) + SiLU + dt softplus ----------------
__global__ void conv_silu_dt(const float* __restrict__ conv_w,
                             const float* __restrict__ conv_b,
                             const float* __restrict__ dt_bias)
{
    const int bl = blockIdx.y;
    const int l = bl & (LL - 1);
    const int c = blockIdx.x * 256 + threadIdx.x;
    float acc = conv_b[c];
    #pragma unroll
    for (int k = 0; k < 4; k++) {
        int ls = l + k - 3;
        if (ls >= 0)
            acc += g_zxbcdt[(size_t)(bl + k - 3) * DIP + DINNER + c] * conv_w[c * 4 + k];
    }
    acc = acc / (1.f + __expf(-acc));
    g_xc[(size_t)bl * CONVD + c] = __uint_as_float(f2tf32(acc));   // tf32-rounded

    if (blockIdx.x == 0 && threadIdx.x < NH) {
        float x = g_zxbcdt[(size_t)bl * DIP + DINNER + CONVD + threadIdx.x] + dt_bias[threadIdx.x];
        float sp = (x > 20.f) ? x : log1pf(__expf(x));
        g_dt[(size_t)bl * NH + threadIdx.x] = sp;
    }
}

// ---------------- per-chunk inclusive cumsum of dA = dt * A ----------------
__global__ void chunk_cumsum(const float* __restrict__ A_log)
{
    const int idx = blockIdx.x;
    const int c = idx % NC;
    const int h = (idx / NC) % NH;
    const int b = idx / (NC * NH);
    const int s = threadIdx.x;
    __shared__ float sh[CS];
    float Ah = -__expf(A_log[h]);
    sh[s] = g_dt[((size_t)b * LL + c * CS + s) * NH + h] * Ah;
    __syncthreads();
    for (int off = 1; off < CS; off <<= 1) {
        float u = (s >= off) ? sh[s - off] : 0.f;
        __syncthreads();
        sh[s] += u;
        __syncthreads();
    }
    g_Acs[(size_t)idx * CS + s] = sh[s];
}

// ---------------- states (tf32 MMA, 256 threads — known-good) ----------------
__global__ __launch_bounds__(256, 2) void states_tf32()
{
    const int z = blockIdx.x;
    const int h = z % NH;
    const int bc = z / NH;
    const int c = bc % NC;
    const int b = bc / NC;
    __shared__ uint32_t Xs[16][132];
    __shared__ uint32_t Bs[16][132];
    __shared__ float ws[CS];
    const int t = threadIdx.x;
    {
        const float* acs = g_Acs + ((size_t)(b * NH + h) * NC + c) * CS;
        float last = acs[CS - 1];
        float dtv = g_dt[((size_t)b * LL + c * CS + t) * NH + h];
        ws[t] = dtv * __expf(last - acs[t]);
    }
    __syncthreads();
    const int lane = t & 31, w = t >> 5;
    const int wm = (w & 1) * 64, wn = (w >> 1) * 32;
    const int lr = t >> 4, lc = (t & 15) * 8;

    float acc[4][4][4];
    #pragma unroll
    for (int i = 0; i < 4; i++)
        #pragma unroll
        for (int j = 0; j < 4; j++)
            #pragma unroll
            for (int q = 0; q < 4; q++) acc[i][j][q] = 0.f;

    const float* xbase = g_xc + ((size_t)b * LL + c * CS) * CONVD + h * HP;
    const float* bbase = g_xc + ((size_t)b * LL + c * CS) * CONVD + DINNER;

    for (int k0 = 0; k0 < CS; k0 += 16) {
        const float wsv = ws[k0 + lr];
        const float* xr = xbase + (size_t)(k0 + lr) * CONVD + lc;
        const float* br = bbase + (size_t)(k0 + lr) * CONVD + lc;
        float4 x0 = *(const float4*)(xr), x1 = *(const float4*)(xr + 4);
        float4 b0 = *(const float4*)(br), b1 = *(const float4*)(br + 4);
        Xs[lr][lc+0]=f2tf32(x0.x*wsv); Xs[lr][lc+1]=f2tf32(x0.y*wsv);
        Xs[lr][lc+2]=f2tf32(x0.z*wsv); Xs[lr][lc+3]=f2tf32(x0.w*wsv);
        Xs[lr][lc+4]=f2tf32(x1.x*wsv); Xs[lr][lc+5]=f2tf32(x1.y*wsv);
        Xs[lr][lc+6]=f2tf32(x1.z*wsv); Xs[lr][lc+7]=f2tf32(x1.w*wsv);
        Bs[lr][lc+0]=__float_as_uint(b0.x); Bs[lr][lc+1]=__float_as_uint(b0.y);
        Bs[lr][lc+2]=__float_as_uint(b0.z); Bs[lr][lc+3]=__float_as_uint(b0.w);
        Bs[lr][lc+4]=__float_as_uint(b1.x); Bs[lr][lc+5]=__float_as_uint(b1.y);
        Bs[lr][lc+6]=__float_as_uint(b1.z); Bs[lr][lc+7]=__float_as_uint(b1.w);
        __syncthreads();
        #pragma unroll
        for (int kk = 0; kk < 16; kk += 8) {
            const int kcol = kk + (lane & 3);
            const int a = lane >> 2;
            uint32_t afr[4][4], bfr[4][2];
            #pragma unroll
            for (int mi = 0; mi < 4; mi++) {
                int r = wm + mi * 16 + a;
                afr[mi][0] = Xs[kcol][r];
                afr[mi][1] = Xs[kcol][r + 8];
                afr[mi][2] = Xs[kcol + 4][r];
                afr[mi][3] = Xs[kcol + 4][r + 8];
            }
            #pragma unroll
            for (int ni = 0; ni < 4; ni++) {
                int cn = wn + ni * 8 + a;
                bfr[ni][0] = Bs[kcol][cn];
                bfr[ni][1] = Bs[kcol + 4][cn];
            }
            #pragma unroll
            for (int mi = 0; mi < 4; mi++)
                #pragma unroll
                for (int ni = 0; ni < 4; ni++)
                    mma_tf32(acc[mi][ni], afr[mi], bfr[ni]);
        }
        __syncthreads();
    }

    float* sout = g_states + (size_t)z * HP * NS;
    const int g = lane >> 2, tt = lane & 3;
    #pragma unroll
    for (int mi = 0; mi < 4; mi++)
        #pragma unroll
        for (int ni = 0; ni < 4; ni++) {
            int row = wm + mi * 16 + g;
            int col = wn + ni * 8 + 2 * tt;
            *(float2*)(sout + (size_t)row * NS + col) =
                make_float2(acc[mi][ni][0], acc[mi][ni][1]);
            *(float2*)(sout + (size_t)(row + 8) * NS + col) =
                make_float2(acc[mi][ni][2], acc[mi][ni][3]);
        }
}

// ---------------- sequential scan over chunks (element-parallel) ----------------
__global__ void chunk_scan()
{
    const int bh = blockIdx.x;
    const int b = bh / NH, h = bh % NH;
    __shared__ float dec[NC];
    if (threadIdx.x < NC)
        dec[threadIdx.x] = __expf(g_Acs[((size_t)(b * NH + h) * NC + threadIdx.x) * CS + CS - 1]);
    __syncthreads();
    const int idx = blockIdx.y * 256 + threadIdx.x;
    float carry = 0.f;
    #pragma unroll
    for (int c = 0; c < NC; c++) {
        size_t base = ((size_t)((b * NC + c) * NH + h)) * HP * NS + idx;
        g_prev[base] = carry;
        carry = carry * dec[c] + g_states[base];
    }
}

// ---------------- Y (tf32 MMA, 256 threads, block-factorized decay exp) ----------------
__global__ __launch_bounds__(256, 2) void y_tf32(const float* __restrict__ Dp)
{
    const int z = blockIdx.y;
    const int h = z % NH;
    const int bc = z / NH;
    const int c = bc % NC;
    const int b = bc / NC;
    const int m0 = blockIdx.x * 128;

    __shared__ float sAcs[CS], sdt[CS];
    __shared__ float sh_e[16];
    __shared__ uint32_t As[128][20];
    __shared__ uint32_t Bt[16][132];
    __shared__ uint32_t B2[128][20];
    const int t = threadIdx.x;
    {
        const float* acs = g_Acs + ((size_t)(b * NH + h) * NC + c) * CS;
        sAcs[t] = acs[t];
        sdt[t] = g_dt[((size_t)b * LL + c * CS + t) * NH + h];
    }
    __syncthreads();

    const int lane = t & 31, w = t >> 5;
    const int wm = (w & 1) * 64, wn = (w >> 1) * 32;
    const int arow = t >> 1, ac8 = (t & 1) * 8;
    const int l_loc = m0 + arow;
    const float acs_l = sAcs[l_loc];
    const float eAl = __expf(acs_l);
    const int xr16 = t >> 4, xc8 = (t & 15) * 8;

    float acc[4][4][4];
    #pragma unroll
    for (int i = 0; i < 4; i++)
        #pragma unroll
        for (int j = 0; j < 4; j++)
            #pragma unroll
            for (int q = 0; q < 4; q++) acc[i][j][q] = 0.f;

    const float* cbt = g_CBT + (size_t)bc * CS * CS;
    const float* cbt_l = cbt + (size_t)l_loc * CS;
    const float* xrow = g_xc + ((size_t)b * LL + c * CS) * CONVD + h * HP;

    // ---- phase 1: intra-chunk, K = m0+128 ----
    // exp(acs_l - acs_s) = exp(acs_l - ref) * exp(ref - acs_s), ref = sAcs[k0+15].
    // sh_e[s'] = exp(ref - acs_s)*dt_s (arg <= 0, safe); e_row once per (row, block)
    // (arg <= ~5 for any block intersecting the mask; fully-masked rows -> 0).
    const int K1 = m0 + 128;
    for (int k0 = 0; k0 < K1; k0 += 16) {
        if (t < 16)
            sh_e[t] = __expf(sAcs[k0 + 15] - sAcs[k0 + t]) * sdt[k0 + t];
        __syncthreads();
        const float e_row = (l_loc >= k0) ? __expf(acs_l - sAcs[k0 + 15]) : 0.f;
        #pragma unroll
        for (int j = 0; j < 8; j++) {
            int s = k0 + ac8 + j;
            float v = 0.f;
            if (s <= l_loc)
                v = cbt_l[s] * e_row * sh_e[ac8 + j];
            As[arow][ac8 + j] = f2tf32(v);
        }
        const float* xr = xrow + (size_t)(k0 + xr16) * CONVD + xc8;
        float4 x0 = *(const float4*)(xr), x1 = *(const float4*)(xr + 4);
        Bt[xr16][xc8+0]=__float_as_uint(x0.x); Bt[xr16][xc8+1]=__float_as_uint(x0.y);
        Bt[xr16][xc8+2]=__float_as_uint(x0.z); Bt[xr16][xc8+3]=__float_as_uint(x0.w);
        Bt[xr16][xc8+4]=__float_as_uint(x1.x); Bt[xr16][xc8+5]=__float_as_uint(x1.y);
        Bt[xr16][xc8+6]=__float_as_uint(x1.z); Bt[xr16][xc8+7]=__float_as_uint(x1.w);
        __syncthreads();
        #pragma unroll
        for (int kk = 0; kk < 16; kk += 8) {
            const int kcol = kk + (lane & 3);
            const int a = lane >> 2;
            uint32_t afr[4][4], bfr[4][2];
            #pragma unroll
            for (int mi = 0; mi < 4; mi++) {
                int r = wm + mi * 16 + a;
                afr[mi][0] = As[r][kcol];
                afr[mi][1] = As[r + 8][kcol];
                afr[mi][2] = As[r][kcol + 4];
                afr[mi][3] = As[r + 8][kcol + 4];
            }
            #pragma unroll
            for (int ni = 0; ni < 4; ni++) {
                int cn = wn + ni * 8 + a;
                bfr[ni][0] = Bt[kcol][cn];
                bfr[ni][1] = Bt[kcol + 4][cn];
            }
            #pragma unroll
            for (int mi = 0; mi < 4; mi++)
                #pragma unroll
                for (int ni = 0; ni < 4; ni++)
                    mma_tf32(acc[mi][ni], afr[mi], bfr[ni]);
        }
        __syncthreads();
    }

    // ---- phase 2: inter-chunk, K = NS = 128 ----
    const float* crow = g_xc + ((size_t)b * LL + c * CS) * CONVD + DINNER + NS;
    const float* prow = g_prev + (size_t)z * HP * NS;
    for (int k0 = 0; k0 < NS; k0 += 16) {
        const float* cr = crow + (size_t)l_loc * CONVD + k0 + ac8;
        float4 c0 = *(const float4*)(cr), c1 = *(const float4*)(cr + 4);
        As[arow][ac8+0]=f2tf32(c0.x*eAl); As[arow][ac8+1]=f2tf32(c0.y*eAl);
        As[arow][ac8+2]=f2tf32(c0.z*eAl); As[arow][ac8+3]=f2tf32(c0.w*eAl);
        As[arow][ac8+4]=f2tf32(c1.x*eAl); As[arow][ac8+5]=f2tf32(c1.y*eAl);
        As[arow][ac8+6]=f2tf32(c1.z*eAl); As[arow][ac8+7]=f2tf32(c1.w*eAl);
        const float* pr = prow + (size_t)arow * NS + k0 + ac8;
        float4 p0 = *(const float4*)(pr), p1 = *(const float4*)(pr + 4);
        B2[arow][ac8+0]=f2tf32(p0.x); B2[arow][ac8+1]=f2tf32(p0.y);
        B2[arow][ac8+2]=f2tf32(p0.z); B2[arow][ac8+3]=f2tf32(p0.w);
        B2[arow][ac8+4]=f2tf32(p1.x); B2[arow][ac8+5]=f2tf32(p1.y);
        B2[arow][ac8+6]=f2tf32(p1.z); B2[arow][ac8+7]=f2tf32(p1.w);
        __syncthreads();
        #pragma unroll
        for (int kk = 0; kk < 16; kk += 8) {
            const int kcol = kk + (lane & 3);
            const int a = lane >> 2;
            uint32_t afr[4][4], bfr[4][2];
            #pragma unroll
            for (int mi = 0; mi < 4; mi++) {
                int r = wm + mi * 16 + a;
                afr[mi][0] = As[r][kcol];
                afr[mi][1] = As[r + 8][kcol];
                afr[mi][2] = As[r][kcol + 4];
                afr[mi][3] = As[r + 8][kcol + 4];
            }
            #pragma unroll
            for (int ni = 0; ni < 4; ni++) {
                int cn = wn + ni * 8 + a;
                bfr[ni][0] = B2[cn][kcol];
                bfr[ni][1] = B2[cn][kcol + 4];
            }
            #pragma unroll
            for (int mi = 0; mi < 4; mi++)
                #pragma unroll
                for (int ni = 0; ni < 4; ni++)
                    mma_tf32(acc[mi][ni], afr[mi], bfr[ni]);
        }
        __syncthreads();
    }

    const float Dh = Dp[h];
    const int g = lane >> 2, tt = lane & 3;
    #pragma unroll
    for (int mi = 0; mi < 4; mi++)
        #pragma unroll
        for (int ni = 0; ni < 4; ni++) {
            int l0 = m0 + wm + mi * 16 + g;
            int p = wn + ni * 8 + 2 * tt;
            float2 xv0 = *(const float2*)(xrow + (size_t)l0 * CONVD + p);
            float2 xv1 = *(const float2*)(xrow + (size_t)(l0 + 8) * CONVD + p);
            float* o0 = g_y + ((size_t)b * LL + c * CS + l0) * DINNER + h * HP + p;
            float* o1 = g_y + ((size_t)b * LL + c * CS + l0 + 8) * DINNER + h * HP + p;
            *(float2*)o0 = make_float2(acc[mi][ni][0] + Dh * xv0.x,
                                       acc[mi][ni][1] + Dh * xv0.y);
            *(float2*)o1 = make_float2(acc[mi][ni][2] + Dh * xv1.x,
                                       acc[mi][ni][3] + Dh * xv1.y);
        }
}

// ---------------- gating (silu(z)) + RMS norm (+ tf32 rounding) ----------------
__global__ void gate_norm(const float* __restrict__ norm_w)
{
    const int row = blockIdx.x;
    const int t = threadIdx.x;
    __shared__ float red[256];
    float vals[8];
    float local = 0.f;
    const float* yrow = g_y + (size_t)row * DINNER;
    const float* zrow = g_zxbcdt + (size_t)row * DIP;
    #pragma unroll
    for (int e = 0; e < 8; e++) {
        int i = e * 256 + t;
        float zv = zrow[i];
        float gv = yrow[i] * zv / (1.f + __expf(-zv));
        vals[e] = gv;
        local += gv * gv;
    }
    red[t] = local;
    __syncthreads();
    for (int off = 128; off > 0; off >>= 1) {
        if (t < off) red[t] += red[t + off];
        __syncthreads();
    }
    float scale = rsqrtf(red[0] / (float)DINNER + 1e-5f);
    float* out = g_y + (size_t)row * DINNER;
    #pragma unroll
    for (int e = 0; e < 8; e++) {
        int i = e * 256 + t;
        out[i] = __uint_as_float(f2tf32(vals[e] * scale * norm_w[i]));
    }
}

// ---------------- host launcher ----------------
extern "C" void kernel_launch(void* const* d_in, const int* in_sizes, int n_in,
                              void* d_out, int out_size)
{
    const float* u       = (const float*)d_in[0];
    const float* W_in    = (const float*)d_in[1];
    const float* conv_w  = (const float*)d_in[2];
    const float* conv_b  = (const float*)d_in[3];
    const float* dt_bias = (const float*)d_in[4];
    const float* A_log   = (const float*)d_in[5];
    const float* Dp      = (const float*)d_in[6];
    const float* norm_w  = (const float*)d_in[7];
    const float* W_out   = (const float*)d_in[8];
    float* out = (float*)d_out;

    float *zx, *xc, *cbt, *y, *ur, *wir, *wor;
    cudaGetSymbolAddress((void**)&zx,  g_zxbcdt);
    cudaGetSymbolAddress((void**)&xc,  g_xc);
    cudaGetSymbolAddress((void**)&cbt, g_CBT);
    cudaGetSymbolAddress((void**)&y,   g_y);
    cudaGetSymbolAddress((void**)&ur,  g_u_r);
    cudaGetSymbolAddress((void**)&wir, g_Win_r);
    cudaGetSymbolAddress((void**)&wor, g_Wout_r);

    const int gemmSmem = GSTG * (AST + BST) * 4;  // 92160 B
    cudaFuncSetAttribute(gemm_tf32_nt,
                         cudaFuncAttributeMaxDynamicSharedMemorySize, gemmSmem);

    // 0) pre-round all dense-GEMM inputs to tf32
    {
        int nu = BB * LL * DM;
        round_tf32<<<(nu / 4 + 255) / 256, 256>>>(u, ur, nu);
        int nwi = DIP * DM;
        round_tf32<<<(nwi / 4 + 255) / 256, 256>>>(W_in, wir, nwi);
        int nwo = DM * DINNER;
        round_tf32<<<(nwo / 4 + 255) / 256, 256>>>(W_out, wor, nwo);
    }

    // 1) in-proj: zxbcdt = u_r @ W_in_r^T   (M=8192, tiles of 256)
    gemm_tf32_nt<<<dim3((DIP + 127) / 128, (BB * LL) / 256, 1), 256, gemmSmem>>>(
        ur, DM, 0, wir, DM, 0, zx, DIP, 0, DIP, DM);

    // 2) conv + silu + dt softplus (tf32-rounded output)
    conv_silu_dt<<<dim3(CONVD / 256, BB * LL), 256>>>(conv_w, conv_b, dt_bias);

    // 3) per-chunk cumsum of dA
    chunk_cumsum<<<BB * NH * NC, CS>>>(A_log);

    // 4) CBT[b,c] = C @ B^T  (M=256 -> one m-tile)
    gemm_tf32_nt<<<dim3(2, 1, BB * NC), 256, gemmSmem>>>(
        xc + (DINNER + NS), CONVD, (long long)CS * CONVD,
        xc + DINNER,        CONVD, (long long)CS * CONVD,
        cbt, CS, (long long)CS * CS,
        CS, NS);

    // 5) per-chunk states (tf32 MMA)
    states_tf32<<<BB * NC * NH, 256>>>();

    // 6) inter-chunk scan (element-parallel)
    chunk_scan<<<dim3(BB * NH, (HP * NS) / 256), 256>>>();

    // 7) Y = diag + off + D*x (tf32 MMA)
    y_tf32<<<dim3(2, BB * NC * NH), 256>>>(Dp);

    // 8) gating + RMS norm (tf32-rounded output)
    gate_norm<<<BB * LL, 256>>>(norm_w);

    // 9) out-proj: out = yg @ W_out_r^T
    gemm_tf32_nt<<<dim3(DM / 128, (BB * LL) / 256, 1), 256, gemmSmem>>>(
        y, DINNER, 0, wor, DINNER, 0, out, DM, 0, DM, DINNER);
}

// round 11
// speedup vs baseline: 1.0347x; 1.0347x over previous
#include <cuda_runtime.h>
#include <math.h>
#include <stdint.h>

// ---------------- problem constants ----------------
#define BB 4
#define LL 2048
#define DM 1024
#define DIP 4368          // 2*D_INNER + 2*D_STATE + NHEADS
#define DINNER 2048
#define CONVD 2304        // D_INNER + 2*D_STATE
#define NH 16
#define HP 128            // head dim
#define NS 128            // state dim
#define CS 256            // chunk size
#define NC 8              // chunks per sequence

// ---------------- scratch (device globals; no allocation) ----------------
__device__ float g_zxbcdt[(size_t)BB * LL * DIP];     // in-proj output
__device__ float g_xc[(size_t)BB * LL * CONVD];       // conv+silu output (tf32-rounded)
__device__ float g_dt[(size_t)BB * LL * NH];          // softplus(dt)
__device__ float g_Acs[(size_t)BB * NH * NC * CS];    // per-chunk inclusive cumsum of dA
__device__ float g_CBT[(size_t)BB * NC * CS * CS];    // C @ B^T per (b,chunk)
__device__ float g_states[(size_t)BB * NC * NH * HP * NS];
__device__ float g_prev[(size_t)BB * NC * NH * HP * NS];
__device__ float g_y[(size_t)BB * LL * DINNER];       // pre-out-proj activations (tf32-rounded)
__device__ float g_u_r[(size_t)BB * LL * DM];         // tf32-rounded u
__device__ float g_Win_r[(size_t)DIP * DM];           // tf32-rounded W_in
__device__ float g_Wout_r[(size_t)DM * DINNER];       // tf32-rounded W_out

// ---------------- tf32 helpers ----------------
__device__ __forceinline__ uint32_t f2tf32(float f) {
    uint32_t r;
    asm("cvt.rna.tf32.f32 %0, %1;" : "=r"(r) : "f"(f));
    return r;
}

__device__ __forceinline__ void mma_tf32(float c[4], const uint32_t a[4], const uint32_t b[2]) {
    asm volatile(
        "mma.sync.aligned.m16n8k8.row.col.f32.tf32.tf32.f32 "
        "{%0,%1,%2,%3}, {%4,%5,%6,%7}, {%8,%9}, {%0,%1,%2,%3};"
        : "+f"(c[0]), "+f"(c[1]), "+f"(c[2]), "+f"(c[3])
        : "r"(a[0]), "r"(a[1]), "r"(a[2]), "r"(a[3]), "r"(b[0]), "r"(b[1]));
}

__device__ __forceinline__ void ldsm4(uint32_t& r0, uint32_t& r1, uint32_t& r2, uint32_t& r3,
                                      uint32_t addr) {
    asm volatile("ldmatrix.sync.aligned.m8n8.x4.shared.b16 {%0,%1,%2,%3}, [%4];"
                 : "=r"(r0), "=r"(r1), "=r"(r2), "=r"(r3) : "r"(addr));
}

__device__ __forceinline__ void cp16(uint32_t dst, const float* src, bool ok) {
    int sz = ok ? 16 : 0;
    asm volatile("cp.async.ca.shared.global [%0], [%1], 16, %2;\n"
                 :: "r"(dst), "l"(src), "r"(sz));
}
#define CP_COMMIT() asm volatile("cp.async.commit_group;\n")
#define CP_WAIT1()  asm volatile("cp.async.wait_group 1;\n" ::: "memory")

// ---------------- elementwise tf32 rounding ----------------
__global__ void round_tf32(const float* __restrict__ s, float* __restrict__ d, int n)
{
    int i = (blockIdx.x * 256 + threadIdx.x) * 4;
    if (i >= n) return;
    float4 v = *(const float4*)(s + i);
    float4 o;
    o.x = __uint_as_float(f2tf32(v.x));
    o.y = __uint_as_float(f2tf32(v.y));
    o.z = __uint_as_float(f2tf32(v.z));
    o.w = __uint_as_float(f2tf32(v.w));
    *(float4*)(d + i) = o;
}

// ---------------- tf32 NT GEMM: 256 threads, 8 warps, 256x128 CTA tile ----------------
// (round-9 known-good: cp.async.ca, 3-stage, ldmatrix, warp tile 64x64)
#define GSTG 3
#define AST (256 * 20)                   // floats per A stage
#define BST (128 * 20)                   // floats per B stage
#define GB_BASE (GSTG * AST)             // B region offset in floats
__global__ __launch_bounds__(256, 1) void gemm_tf32_nt(
    const float* __restrict__ A, int lda, long long sA,
    const float* __restrict__ B, int ldb, long long sB,
    float* __restrict__ C, int ldc, long long sC,
    int N, int K)
{
    extern __shared__ float sm[];
    const float* Ab = A + (size_t)blockIdx.z * sA;
    const float* Bb = B + (size_t)blockIdx.z * sB;
    float* Cb = C + (size_t)blockIdx.z * sC;
    const int m0 = blockIdx.y * 256, n0 = blockIdx.x * 128;
    const int t = threadIdx.x;
    const int lane = t & 31, w = t >> 5;
    const int wm = (w >> 1) * 64, wn = (w & 1) * 64;

    const bool bldr = (t < 128);
    const bool bok = bldr && ((n0 + t) < N);
    const float* aS = Ab + (size_t)(m0 + t) * lda;
    const float* bS = Bb + (size_t)(bok ? n0 + t : 0) * ldb;
    const uint32_t smBase = (uint32_t)__cvta_generic_to_shared(sm);
    const uint32_t dA = smBase + (t * 20) * 4;
    const uint32_t dB = smBase + (GB_BASE + t * 20) * 4;

    const int rowA = wm + (lane & 15);
    const int colA = (lane >> 4) * 4;
    const int rowB = wn + ((lane >> 4) << 3) + (lane & 7);
    const int colB = ((lane >> 3) & 1) * 4;

    float acc[4][8][4];
    #pragma unroll
    for (int i = 0; i < 4; i++)
        #pragma unroll
        for (int j = 0; j < 8; j++)
            #pragma unroll
            for (int q = 0; q < 4; q++) acc[i][j][q] = 0.f;

    const int nIter = K >> 4;
    #pragma unroll
    for (int s = 0; s < GSTG - 1; s++) {
        const uint32_t offA = s * AST * 4;
        const uint32_t offB = s * BST * 4;
        const int k0 = s << 4;
        cp16(dA + offA,      aS + k0,      true);
        cp16(dA + offA + 16, aS + k0 + 4,  true);
        cp16(dA + offA + 32, aS + k0 + 8,  true);
        cp16(dA + offA + 48, aS + k0 + 12, true);
        if (bldr) {
            cp16(dB + offB,      bS + k0,      bok);
            cp16(dB + offB + 16, bS + k0 + 4,  bok);
            cp16(dB + offB + 32, bS + k0 + 8,  bok);
            cp16(dB + offB + 48, bS + k0 + 12, bok);
        }
        CP_COMMIT();
    }

    for (int it = 0; it < nIter; it++) {
        CP_WAIT1();
        __syncthreads();
        const int pf = it + GSTG - 1;
        if (pf < nIter) {
            const uint32_t offA = (pf % GSTG) * AST * 4;
            const uint32_t offB = (pf % GSTG) * BST * 4;
            const int k0 = pf << 4;
            cp16(dA + offA,      aS + k0,      true);
            cp16(dA + offA + 16, aS + k0 + 4,  true);
            cp16(dA + offA + 32, aS + k0 + 8,  true);
            cp16(dA + offA + 48, aS + k0 + 12, true);
            if (bldr) {
                cp16(dB + offB,      bS + k0,      bok);
                cp16(dB + offB + 16, bS + k0 + 4,  bok);
                cp16(dB + offB + 32, bS + k0 + 8,  bok);
                cp16(dB + offB + 48, bS + k0 + 12, bok);
            }
        }
        CP_COMMIT();

        const uint32_t aOct = smBase + (it % GSTG) * AST * 4 + (rowA * 20 + colA) * 4;
        const uint32_t bOct = smBase + GB_BASE * 4 + (it % GSTG) * BST * 4
                              + (rowB * 20 + colB) * 4;
        #pragma unroll
        for (int kk = 0; kk < 16; kk += 8) {
            uint32_t afr[4][4], bfr[8][2];
            #pragma unroll
            for (int mi = 0; mi < 4; mi++)
                ldsm4(afr[mi][0], afr[mi][1], afr[mi][2], afr[mi][3],
                      aOct + kk * 4 + mi * (16 * 20 * 4));
            #pragma unroll
            for (int j = 0; j < 4; j++)
                ldsm4(bfr[2 * j][0], bfr[2 * j][1], bfr[2 * j + 1][0], bfr[2 * j + 1][1],
                      bOct + kk * 4 + j * (16 * 20 * 4));
            #pragma unroll
            for (int mi = 0; mi < 4; mi++)
                #pragma unroll
                for (int ni = 0; ni < 8; ni++)
                    mma_tf32(acc[mi][ni], afr[mi], bfr[ni]);
        }
    }

    const int g = lane >> 2, tt = lane & 3;
    #pragma unroll
    for (int mi = 0; mi < 4; mi++) {
        #pragma unroll
        for (int ni = 0; ni < 8; ni++) {
            int row = m0 + wm + mi * 16 + g;
            int col = n0 + wn + ni * 8 + 2 * tt;
            if (col < N) {
                *(float2*)(Cb + (size_t)row * ldc + col) =
                    make_float2(acc[mi][ni][0], acc[mi][ni][1]);
                *(float2*)(Cb + (size_t)(row + 8) * ldc + col) =
                    make_float2(acc[mi][ni][2], acc[mi][ni][3]);
            }
        }
    }
}

// ---------------- depthwise conv (K=4) + SiLU + dt softplus ----------------
__global__ void conv_silu_dt(const float* __restrict__ conv_w,
                             const float* __restrict__ conv_b,
                             const float* __restrict__ dt_bias)
{
    const int bl = blockIdx.y;
    const int l = bl & (LL - 1);
    const int c = blockIdx.x * 256 + threadIdx.x;
    float acc = conv_b[c];
    #pragma unroll
    for (int k = 0; k < 4; k++) {
        int ls = l + k - 3;
        if (ls >= 0)
            acc += g_zxbcdt[(size_t)(bl + k - 3) * DIP + DINNER + c] * conv_w[c * 4 + k];
    }
    acc = acc / (1.f + __expf(-acc));
    g_xc[(size_t)bl * CONVD + c] = __uint_as_float(f2tf32(acc));   // tf32-rounded

    if (blockIdx.x == 0 && threadIdx.x < NH) {
        float x = g_zxbcdt[(size_t)bl * DIP + DINNER + CONVD + threadIdx.x] + dt_bias[threadIdx.x];
        float sp = (x > 20.f) ? x : log1pf(__expf(x));
        g_dt[(size_t)bl * NH + threadIdx.x] = sp;
    }
}

// ---------------- per-chunk inclusive cumsum of dA = dt * A ----------------
__global__ void chunk_cumsum(const float* __restrict__ A_log)
{
    const int idx = blockIdx.x;
    const int c = idx % NC;
    const int h = (idx / NC) % NH;
    const int b = idx / (NC * NH);
    const int s = threadIdx.x;
    __shared__ float sh[CS];
    float Ah = -__expf(A_log[h]);
    sh[s] = g_dt[((size_t)b * LL + c * CS + s) * NH + h] * Ah;
    __syncthreads();
    for (int off = 1; off < CS; off <<= 1) {
        float u = (s >= off) ? sh[s - off] : 0.f;
        __syncthreads();
        sh[s] += u;
        __syncthreads();
    }
    g_Acs[(size_t)idx * CS + s] = sh[s];
}

// ---------------- states (tf32 MMA, 256 threads — known-good) ----------------
__global__ __launch_bounds__(256, 2) void states_tf32()
{
    const int z = blockIdx.x;
    const int h = z % NH;
    const int bc = z / NH;
    const int c = bc % NC;
    const int b = bc / NC;
    __shared__ uint32_t Xs[16][132];
    __shared__ uint32_t Bs[16][132];
    __shared__ float ws[CS];
    const int t = threadIdx.x;
    {
        const float* acs = g_Acs + ((size_t)(b * NH + h) * NC + c) * CS;
        float last = acs[CS - 1];
        float dtv = g_dt[((size_t)b * LL + c * CS + t) * NH + h];
        ws[t] = dtv * __expf(last - acs[t]);
    }
    __syncthreads();
    const int lane = t & 31, w = t >> 5;
    const int wm = (w & 1) * 64, wn = (w >> 1) * 32;
    const int lr = t >> 4, lc = (t & 15) * 8;

    float acc[4][4][4];
    #pragma unroll
    for (int i = 0; i < 4; i++)
        #pragma unroll
        for (int j = 0; j < 4; j++)
            #pragma unroll
            for (int q = 0; q < 4; q++) acc[i][j][q] = 0.f;

    const float* xbase = g_xc + ((size_t)b * LL + c * CS) * CONVD + h * HP;
    const float* bbase = g_xc + ((size_t)b * LL + c * CS) * CONVD + DINNER;

    for (int k0 = 0; k0 < CS; k0 += 16) {
        const float wsv = ws[k0 + lr];
        const float* xr = xbase + (size_t)(k0 + lr) * CONVD + lc;
        const float* br = bbase + (size_t)(k0 + lr) * CONVD + lc;
        float4 x0 = *(const float4*)(xr), x1 = *(const float4*)(xr + 4);
        float4 b0 = *(const float4*)(br), b1 = *(const float4*)(br + 4);
        Xs[lr][lc+0]=f2tf32(x0.x*wsv); Xs[lr][lc+1]=f2tf32(x0.y*wsv);
        Xs[lr][lc+2]=f2tf32(x0.z*wsv); Xs[lr][lc+3]=f2tf32(x0.w*wsv);
        Xs[lr][lc+4]=f2tf32(x1.x*wsv); Xs[lr][lc+5]=f2tf32(x1.y*wsv);
        Xs[lr][lc+6]=f2tf32(x1.z*wsv); Xs[lr][lc+7]=f2tf32(x1.w*wsv);
        Bs[lr][lc+0]=__float_as_uint(b0.x); Bs[lr][lc+1]=__float_as_uint(b0.y);
        Bs[lr][lc+2]=__float_as_uint(b0.z); Bs[lr][lc+3]=__float_as_uint(b0.w);
        Bs[lr][lc+4]=__float_as_uint(b1.x); Bs[lr][lc+5]=__float_as_uint(b1.y);
        Bs[lr][lc+6]=__float_as_uint(b1.z); Bs[lr][lc+7]=__float_as_uint(b1.w);
        __syncthreads();
        #pragma unroll
        for (int kk = 0; kk < 16; kk += 8) {
            const int kcol = kk + (lane & 3);
            const int a = lane >> 2;
            uint32_t afr[4][4], bfr[4][2];
            #pragma unroll
            for (int mi = 0; mi < 4; mi++) {
                int r = wm + mi * 16 + a;
                afr[mi][0] = Xs[kcol][r];
                afr[mi][1] = Xs[kcol][r + 8];
                afr[mi][2] = Xs[kcol + 4][r];
                afr[mi][3] = Xs[kcol + 4][r + 8];
            }
            #pragma unroll
            for (int ni = 0; ni < 4; ni++) {
                int cn = wn + ni * 8 + a;
                bfr[ni][0] = Bs[kcol][cn];
                bfr[ni][1] = Bs[kcol + 4][cn];
            }
            #pragma unroll
            for (int mi = 0; mi < 4; mi++)
                #pragma unroll
                for (int ni = 0; ni < 4; ni++)
                    mma_tf32(acc[mi][ni], afr[mi], bfr[ni]);
        }
        __syncthreads();
    }

    float* sout = g_states + (size_t)z * HP * NS;
    const int g = lane >> 2, tt = lane & 3;
    #pragma unroll
    for (int mi = 0; mi < 4; mi++)
        #pragma unroll
        for (int ni = 0; ni < 4; ni++) {
            int row = wm + mi * 16 + g;
            int col = wn + ni * 8 + 2 * tt;
            *(float2*)(sout + (size_t)row * NS + col) =
                make_float2(acc[mi][ni][0], acc[mi][ni][1]);
            *(float2*)(sout + (size_t)(row + 8) * NS + col) =
                make_float2(acc[mi][ni][2], acc[mi][ni][3]);
        }
}

// ---------------- sequential scan over chunks (element-parallel) ----------------
__global__ void chunk_scan()
{
    const int bh = blockIdx.x;
    const int b = bh / NH, h = bh % NH;
    __shared__ float dec[NC];
    if (threadIdx.x < NC)
        dec[threadIdx.x] = __expf(g_Acs[((size_t)(b * NH + h) * NC + threadIdx.x) * CS + CS - 1]);
    __syncthreads();
    const int idx = blockIdx.y * 256 + threadIdx.x;
    float carry = 0.f;
    #pragma unroll
    for (int c = 0; c < NC; c++) {
        size_t base = ((size_t)((b * NC + c) * NH + h)) * HP * NS + idx;
        g_prev[base] = carry;
        carry = carry * dec[c] + g_states[base];
    }
}

// ---------------- Y (tf32 MMA, 256 threads, block-factorized decay exp) ----------------
__global__ __launch_bounds__(256, 2) void y_tf32(const float* __restrict__ Dp)
{
    const int z = blockIdx.y;
    const int h = z % NH;
    const int bc = z / NH;
    const int c = bc % NC;
    const int b = bc / NC;
    const int m0 = blockIdx.x * 128;

    __shared__ float sAcs[CS], sdt[CS];
    __shared__ float sh_e[16];
    __shared__ uint32_t As[128][20];
    __shared__ uint32_t Bt[16][132];
    __shared__ uint32_t B2[128][20];
    const int t = threadIdx.x;
    {
        const float* acs = g_Acs + ((size_t)(b * NH + h) * NC + c) * CS;
        sAcs[t] = acs[t];
        sdt[t] = g_dt[((size_t)b * LL + c * CS + t) * NH + h];
    }
    __syncthreads();

    const int lane = t & 31, w = t >> 5;
    const int wm = (w & 1) * 64, wn = (w >> 1) * 32;
    const int arow = t >> 1, ac8 = (t & 1) * 8;
    const int l_loc = m0 + arow;
    const float acs_l = sAcs[l_loc];
    const float eAl = __expf(acs_l);
    const int xr16 = t >> 4, xc8 = (t & 15) * 8;

    float acc[4][4][4];
    #pragma unroll
    for (int i = 0; i < 4; i++)
        #pragma unroll
        for (int j = 0; j < 4; j++)
            #pragma unroll
            for (int q = 0; q < 4; q++) acc[i][j][q] = 0.f;

    const float* cbt = g_CBT + (size_t)bc * CS * CS;
    const float* cbt_l = cbt + (size_t)l_loc * CS;
    const float* xrow = g_xc + ((size_t)b * LL + c * CS) * CONVD + h * HP;

    // ---- phase 1: intra-chunk, K = m0+128 (factorized decay exp) ----
    const int K1 = m0 + 128;
    for (int k0 = 0; k0 < K1; k0 += 16) {
        if (t < 16)
            sh_e[t] = __expf(sAcs[k0 + 15] - sAcs[k0 + t]) * sdt[k0 + t];
        __syncthreads();
        const float e_row = (l_loc >= k0) ? __expf(acs_l - sAcs[k0 + 15]) : 0.f;
        #pragma unroll
        for (int j = 0; j < 8; j++) {
            int s = k0 + ac8 + j;
            float v = 0.f;
            if (s <= l_loc)
                v = cbt_l[s] * e_row * sh_e[ac8 + j];
            As[arow][ac8 + j] = f2tf32(v);
        }
        const float* xr = xrow + (size_t)(k0 + xr16) * CONVD + xc8;
        float4 x0 = *(const float4*)(xr), x1 = *(const float4*)(xr + 4);
        Bt[xr16][xc8+0]=__float_as_uint(x0.x); Bt[xr16][xc8+1]=__float_as_uint(x0.y);
        Bt[xr16][xc8+2]=__float_as_uint(x0.z); Bt[xr16][xc8+3]=__float_as_uint(x0.w);
        Bt[xr16][xc8+4]=__float_as_uint(x1.x); Bt[xr16][xc8+5]=__float_as_uint(x1.y);
        Bt[xr16][xc8+6]=__float_as_uint(x1.z); Bt[xr16][xc8+7]=__float_as_uint(x1.w);
        __syncthreads();
        #pragma unroll
        for (int kk = 0; kk < 16; kk += 8) {
            const int kcol = kk + (lane & 3);
            const int a = lane >> 2;
            uint32_t afr[4][4], bfr[4][2];
            #pragma unroll
            for (int mi = 0; mi < 4; mi++) {
                int r = wm + mi * 16 + a;
                afr[mi][0] = As[r][kcol];
                afr[mi][1] = As[r + 8][kcol];
                afr[mi][2] = As[r][kcol + 4];
                afr[mi][3] = As[r + 8][kcol + 4];
            }
            #pragma unroll
            for (int ni = 0; ni < 4; ni++) {
                int cn = wn + ni * 8 + a;
                bfr[ni][0] = Bt[kcol][cn];
                bfr[ni][1] = Bt[kcol + 4][cn];
            }
            #pragma unroll
            for (int mi = 0; mi < 4; mi++)
                #pragma unroll
                for (int ni = 0; ni < 4; ni++)
                    mma_tf32(acc[mi][ni], afr[mi], bfr[ni]);
        }
        __syncthreads();
    }

    // ---- phase 2: inter-chunk, K = NS = 128 ----
    const float* crow = g_xc + ((size_t)b * LL + c * CS) * CONVD + DINNER + NS;
    const float* prow = g_prev + (size_t)z * HP * NS;
    for (int k0 = 0; k0 < NS; k0 += 16) {
        const float* cr = crow + (size_t)l_loc * CONVD + k0 + ac8;
        float4 c0 = *(const float4*)(cr), c1 = *(const float4*)(cr + 4);
        As[arow][ac8+0]=f2tf32(c0.x*eAl); As[arow][ac8+1]=f2tf32(c0.y*eAl);
        As[arow][ac8+2]=f2tf32(c0.z*eAl); As[arow][ac8+3]=f2tf32(c0.w*eAl);
        As[arow][ac8+4]=f2tf32(c1.x*eAl); As[arow][ac8+5]=f2tf32(c1.y*eAl);
        As[arow][ac8+6]=f2tf32(c1.z*eAl); As[arow][ac8+7]=f2tf32(c1.w*eAl);
        const float* pr = prow + (size_t)arow * NS + k0 + ac8;
        float4 p0 = *(const float4*)(pr), p1 = *(const float4*)(pr + 4);
        B2[arow][ac8+0]=f2tf32(p0.x); B2[arow][ac8+1]=f2tf32(p0.y);
        B2[arow][ac8+2]=f2tf32(p0.z); B2[arow][ac8+3]=f2tf32(p0.w);
        B2[arow][ac8+4]=f2tf32(p1.x); B2[arow][ac8+5]=f2tf32(p1.y);
        B2[arow][ac8+6]=f2tf32(p1.z); B2[arow][ac8+7]=f2tf32(p1.w);
        __syncthreads();
        #pragma unroll
        for (int kk = 0; kk < 16; kk += 8) {
            const int kcol = kk + (lane & 3);
            const int a = lane >> 2;
            uint32_t afr[4][4], bfr[4][2];
            #pragma unroll
            for (int mi = 0; mi < 4; mi++) {
                int r = wm + mi * 16 + a;
                afr[mi][0] = As[r][kcol];
                afr[mi][1] = As[r + 8][kcol];
                afr[mi][2] = As[r][kcol + 4];
                afr[mi][3] = As[r + 8][kcol + 4];
            }
            #pragma unroll
            for (int ni = 0; ni < 4; ni++) {
                int cn = wn + ni * 8 + a;
                bfr[ni][0] = B2[cn][kcol];
                bfr[ni][1] = B2[cn][kcol + 4];
            }
            #pragma unroll
            for (int mi = 0; mi < 4; mi++)
                #pragma unroll
                for (int ni = 0; ni < 4; ni++)
                    mma_tf32(acc[mi][ni], afr[mi], bfr[ni]);
        }
        __syncthreads();
    }

    const float Dh = Dp[h];
    const int g = lane >> 2, tt = lane & 3;
    #pragma unroll
    for (int mi = 0; mi < 4; mi++)
        #pragma unroll
        for (int ni = 0; ni < 4; ni++) {
            int l0 = m0 + wm + mi * 16 + g;
            int p = wn + ni * 8 + 2 * tt;
            float2 xv0 = *(const float2*)(xrow + (size_t)l0 * CONVD + p);
            float2 xv1 = *(const float2*)(xrow + (size_t)(l0 + 8) * CONVD + p);
            float* o0 = g_y + ((size_t)b * LL + c * CS + l0) * DINNER + h * HP + p;
            float* o1 = g_y + ((size_t)b * LL + c * CS + l0 + 8) * DINNER + h * HP + p;
            *(float2*)o0 = make_float2(acc[mi][ni][0] + Dh * xv0.x,
                                       acc[mi][ni][1] + Dh * xv0.y);
            *(float2*)o1 = make_float2(acc[mi][ni][2] + Dh * xv1.x,
                                       acc[mi][ni][3] + Dh * xv1.y);
        }
}

// ---------------- gating (silu(z)) + RMS norm (+ tf32 rounding) ----------------
__global__ void gate_norm(const float* __restrict__ norm_w)
{
    const int row = blockIdx.x;
    const int t = threadIdx.x;
    __shared__ float red[256];
    float vals[8];
    float local = 0.f;
    const float* yrow = g_y + (size_t)row * DINNER;
    const float* zrow = g_zxbcdt + (size_t)row * DIP;
    #pragma unroll
    for (int e = 0; e < 8; e++) {
        int i = e * 256 + t;
        float zv = zrow[i];
        float gv = yrow[i] * zv / (1.f + __expf(-zv));
        vals[e] = gv;
        local += gv * gv;
    }
    red[t] = local;
    __syncthreads();
    for (int off = 128; off > 0; off >>= 1) {
        if (t < off) red[t] += red[t + off];
        __syncthreads();
    }
    float scale = rsqrtf(red[0] / (float)DINNER + 1e-5f);
    float* out = g_y + (size_t)row * DINNER;
    #pragma unroll
    for (int e = 0; e < 8; e++) {
        int i = e * 256 + t;
        out[i] = __uint_as_float(f2tf32(vals[e] * scale * norm_w[i]));
    }
}

// ---------------- host launcher ----------------
extern "C" void kernel_launch(void* const* d_in, const int* in_sizes, int n_in,
                              void* d_out, int out_size)
{
    const float* u       = (const float*)d_in[0];
    const float* W_in    = (const float*)d_in[1];
    const float* conv_w  = (const float*)d_in[2];
    const float* conv_b  = (const float*)d_in[3];
    const float* dt_bias = (const float*)d_in[4];
    const float* A_log   = (const float*)d_in[5];
    const float* Dp      = (const float*)d_in[6];
    const float* norm_w  = (const float*)d_in[7];
    const float* W_out   = (const float*)d_in[8];
    float* out = (float*)d_out;

    float *zx, *xc, *cbt, *y, *ur, *wir, *wor;
    cudaGetSymbolAddress((void**)&zx,  g_zxbcdt);
    cudaGetSymbolAddress((void**)&xc,  g_xc);
    cudaGetSymbolAddress((void**)&cbt, g_CBT);
    cudaGetSymbolAddress((void**)&y,   g_y);
    cudaGetSymbolAddress((void**)&ur,  g_u_r);
    cudaGetSymbolAddress((void**)&wir, g_Win_r);
    cudaGetSymbolAddress((void**)&wor, g_Wout_r);

    const int gemmSmem = GSTG * (AST + BST) * 4;  // 92160 B
    cudaFuncSetAttribute(gemm_tf32_nt,
                         cudaFuncAttributeMaxDynamicSharedMemorySize, gemmSmem);

    // 0) pre-round all dense-GEMM inputs to tf32
    {
        int nu = BB * LL * DM;
        round_tf32<<<(nu / 4 + 255) / 256, 256>>>(u, ur, nu);
        int nwi = DIP * DM;
        round_tf32<<<(nwi / 4 + 255) / 256, 256>>>(W_in, wir, nwi);
        int nwo = DM * DINNER;
        round_tf32<<<(nwo / 4 + 255) / 256, 256>>>(W_out, wor, nwo);
    }

    // 1) in-proj: zxbcdt = u_r @ W_in_r^T   (M=8192, tiles of 256)
    gemm_tf32_nt<<<dim3((DIP + 127) / 128, (BB * LL) / 256, 1), 256, gemmSmem>>>(
        ur, DM, 0, wir, DM, 0, zx, DIP, 0, DIP, DM);

    // 2) conv + silu + dt softplus (tf32-rounded output)
    conv_silu_dt<<<dim3(CONVD / 256, BB * LL), 256>>>(conv_w, conv_b, dt_bias);

    // 3) per-chunk cumsum of dA
    chunk_cumsum<<<BB * NH * NC, CS>>>(A_log);

    // 4) CBT[b,c] = C @ B^T  (M=256 -> one m-tile)
    gemm_tf32_nt<<<dim3(2, 1, BB * NC), 256, gemmSmem>>>(
        xc + (DINNER + NS), CONVD, (long long)CS * CONVD,
        xc + DINNER,        CONVD, (long long)CS * CONVD,
        cbt, CS, (long long)CS * CS,
        CS, NS);

    // 5) per-chunk states (tf32 MMA)
    states_tf32<<<BB * NC * NH, 256>>>();

    // 6) inter-chunk scan (element-parallel)
    chunk_scan<<<dim3(BB * NH, (HP * NS) / 256), 256>>>();

    // 7) Y = diag + off + D*x (tf32 MMA)
    y_tf32<<<dim3(2, BB * NC * NH), 256>>>(Dp);

    // 8) gating + RMS norm (tf32-rounded output)
    gate_norm<<<BB * LL, 256>>>(norm_w);

    // 9) out-proj: out = yg @ W_out_r^T
    gemm_tf32_nt<<<dim3(DM / 128, (BB * LL) / 256, 1), 256, gemmSmem>>>(
        y, DINNER, 0, wor, DINNER, 0, out, DM, 0, DM, DINNER);
}

// round 12
// speedup vs baseline: 1.5443x; 1.4925x over previous
#include <cuda_runtime.h>
#include <cuda_fp16.h>
#include <math.h>
#include <stdint.h>

// ---------------- problem constants ----------------
#define BB 4
#define LL 2048
#define DM 1024
#define DIP 4368          // 2*D_INNER + 2*D_STATE + NHEADS
#define DINNER 2048
#define CONVD 2304        // D_INNER + 2*D_STATE
#define NH 16
#define HP 128            // head dim
#define NS 128            // state dim
#define CS 256            // chunk size
#define NC 8              // chunks per sequence

// ---------------- scratch (device globals; no allocation) ----------------
__device__ float g_zxbcdt[(size_t)BB * LL * DIP];     // in-proj output
__device__ float g_xc[(size_t)BB * LL * CONVD];       // conv+silu output (tf32-rounded)
__device__ float g_dt[(size_t)BB * LL * NH];          // softplus(dt)
__device__ float g_Acs[(size_t)BB * NH * NC * CS];    // per-chunk inclusive cumsum of dA
__device__ float g_CBT[(size_t)BB * NC * CS * CS];    // C @ B^T per (b,chunk)
__device__ float g_states[(size_t)BB * NC * NH * HP * NS];
__device__ float g_prev[(size_t)BB * NC * NH * HP * NS];
__device__ float g_y[(size_t)BB * LL * DINNER];       // pre-out-proj activations
__device__ __half g_u_h[(size_t)BB * LL * DM];        // fp16 u
__device__ __half g_Win_h[(size_t)DIP * DM];          // fp16 W_in
__device__ __half g_Wout_h[(size_t)DM * DINNER];      // fp16 W_out
__device__ __half g_bc_h[(size_t)BB * LL * 2 * NS];   // fp16 B|C (conv output cols)
__device__ __half g_yg_h[(size_t)BB * LL * DINNER];   // fp16 gated+normed y

// ---------------- helpers ----------------
__device__ __forceinline__ uint32_t f2tf32(float f) {
    uint32_t r;
    asm("cvt.rna.tf32.f32 %0, %1;" : "=r"(r) : "f"(f));
    return r;
}

__device__ __forceinline__ void mma_tf32(float c[4], const uint32_t a[4], const uint32_t b[2]) {
    asm volatile(
        "mma.sync.aligned.m16n8k8.row.col.f32.tf32.tf32.f32 "
        "{%0,%1,%2,%3}, {%4,%5,%6,%7}, {%8,%9}, {%0,%1,%2,%3};"
        : "+f"(c[0]), "+f"(c[1]), "+f"(c[2]), "+f"(c[3])
        : "r"(a[0]), "r"(a[1]), "r"(a[2]), "r"(a[3]), "r"(b[0]), "r"(b[1]));
}

__device__ __forceinline__ void mma_fp16(float c[4], const uint32_t a[4], const uint32_t b[2]) {
    asm volatile(
        "mma.sync.aligned.m16n8k16.row.col.f32.f16.f16.f32 "
        "{%0,%1,%2,%3}, {%4,%5,%6,%7}, {%8,%9}, {%0,%1,%2,%3};"
        : "+f"(c[0]), "+f"(c[1]), "+f"(c[2]), "+f"(c[3])
        : "r"(a[0]), "r"(a[1]), "r"(a[2]), "r"(a[3]), "r"(b[0]), "r"(b[1]));
}

__device__ __forceinline__ void ldsm4(uint32_t& r0, uint32_t& r1, uint32_t& r2, uint32_t& r3,
                                      uint32_t addr) {
    asm volatile("ldmatrix.sync.aligned.m8n8.x4.shared.b16 {%0,%1,%2,%3}, [%4];"
                 : "=r"(r0), "=r"(r1), "=r"(r2), "=r"(r3) : "r"(addr));
}

__device__ __forceinline__ void cp16(uint32_t dst, const void* src, bool ok) {
    int sz = ok ? 16 : 0;
    asm volatile("cp.async.ca.shared.global [%0], [%1], 16, %2;\n"
                 :: "r"(dst), "l"(src), "r"(sz));
}
#define CP_COMMIT() asm volatile("cp.async.commit_group;\n")
#define CP_WAIT1()  asm volatile("cp.async.wait_group 1;\n" ::: "memory")

// ---------------- elementwise fp32 -> fp16 ----------------
__global__ void round_fp16(const float* __restrict__ s, __half* __restrict__ d, int n)
{
    int i = (blockIdx.x * 256 + threadIdx.x) * 4;
    if (i >= n) return;
    float4 v = *(const float4*)(s + i);
    __half2 h0 = __floats2half2_rn(v.x, v.y);
    __half2 h1 = __floats2half2_rn(v.z, v.w);
    *(__half2*)(d + i) = h0;
    *(__half2*)(d + i + 2) = h1;
}

// ---------------- fp16 NT GEMM: 256 threads, 8 warps, 256x128 CTA tile ----------------
// C[m,n] = sum_k A[m,k]*B[n,k], fp16 inputs, fp32 accumulate.
// Warp grid 4(M) x 2(N), warp tile 64x64, BK=32 halves, 3-stage cp.async, ldmatrix.
// Rows: 64B payload (32 halves) + 16B pad = 80B stride (conflict-free, same bank
// math as stride-20-float). M%256==0, K%32==0 required; N guarded.
// Dynamic smem: 3*(256*80 + 128*80) = 92160 B.
#define GSTG 3
#define A_STG_B (256 * 80)
#define B_STG_B (128 * 80)
#define GB_OFF (GSTG * A_STG_B)
__global__ __launch_bounds__(256, 1) void gemm_fp16_nt(
    const __half* __restrict__ A, int lda, long long sA,
    const __half* __restrict__ B, int ldb, long long sB,
    float* __restrict__ C, int ldc, long long sC,
    int N, int K)
{
    extern __shared__ char smraw[];
    const __half* Ab = A + (size_t)blockIdx.z * sA;
    const __half* Bb = B + (size_t)blockIdx.z * sB;
    float* Cb = C + (size_t)blockIdx.z * sC;
    const int m0 = blockIdx.y * 256, n0 = blockIdx.x * 128;
    const int t = threadIdx.x;
    const int lane = t & 31, w = t >> 5;
    const int wm = (w >> 1) * 64, wn = (w & 1) * 64;

    const bool bldr = (t < 128);
    const bool bok = bldr && ((n0 + t) < N);
    const __half* aS = Ab + (size_t)(m0 + t) * lda;
    const __half* bS = Bb + (size_t)(bok ? n0 + t : 0) * ldb;
    const uint32_t smBase = (uint32_t)__cvta_generic_to_shared(smraw);
    const uint32_t dA = smBase + t * 80;
    const uint32_t dB = smBase + GB_OFF + t * 80;

    // ldmatrix per-thread source addresses (bytes)
    const uint32_t aFragOff = (uint32_t)((wm + (lane & 15)) * 80 + (lane >> 4) * 16);
    const uint32_t bFragOff = (uint32_t)((wn + ((lane >> 4) << 3) + (lane & 7)) * 80
                                         + ((lane >> 3) & 1) * 16);

    float acc[4][8][4];
    #pragma unroll
    for (int i = 0; i < 4; i++)
        #pragma unroll
        for (int j = 0; j < 8; j++)
            #pragma unroll
            for (int q = 0; q < 4; q++) acc[i][j][q] = 0.f;

    const int nIter = K >> 5;                 // BK = 32 halves
    #pragma unroll
    for (int s = 0; s < GSTG - 1; s++) {
        const uint32_t offA = s * A_STG_B;
        const uint32_t offB = s * B_STG_B;
        const int k0 = s << 5;
        cp16(dA + offA,      aS + k0,      true);
        cp16(dA + offA + 16, aS + k0 + 8,  true);
        cp16(dA + offA + 32, aS + k0 + 16, true);
        cp16(dA + offA + 48, aS + k0 + 24, true);
        if (bldr) {
            cp16(dB + offB,      bS + k0,      bok);
            cp16(dB + offB + 16, bS + k0 + 8,  bok);
            cp16(dB + offB + 32, bS + k0 + 16, bok);
            cp16(dB + offB + 48, bS + k0 + 24, bok);
        }
        CP_COMMIT();
    }

    for (int it = 0; it < nIter; it++) {
        CP_WAIT1();
        __syncthreads();
        const int pf = it + GSTG - 1;
        if (pf < nIter) {
            const uint32_t offA = (pf % GSTG) * A_STG_B;
            const uint32_t offB = (pf % GSTG) * B_STG_B;
            const int k0 = pf << 5;
            cp16(dA + offA,      aS + k0,      true);
            cp16(dA + offA + 16, aS + k0 + 8,  true);
            cp16(dA + offA + 32, aS + k0 + 16, true);
            cp16(dA + offA + 48, aS + k0 + 24, true);
            if (bldr) {
                cp16(dB + offB,      bS + k0,      bok);
                cp16(dB + offB + 16, bS + k0 + 8,  bok);
                cp16(dB + offB + 32, bS + k0 + 16, bok);
                cp16(dB + offB + 48, bS + k0 + 24, bok);
            }
        }
        CP_COMMIT();

        const uint32_t aOct = smBase + (it % GSTG) * A_STG_B + aFragOff;
        const uint32_t bOct = smBase + GB_OFF + (it % GSTG) * B_STG_B + bFragOff;
        #pragma unroll
        for (int kk = 0; kk < 64; kk += 32) {       // two k16 chunks per iter
            uint32_t afr[4][4], bfr[8][2];
            #pragma unroll
            for (int mi = 0; mi < 4; mi++)
                ldsm4(afr[mi][0], afr[mi][1], afr[mi][2], afr[mi][3],
                      aOct + kk + mi * (16 * 80));
            #pragma unroll
            for (int j = 0; j < 4; j++)
                ldsm4(bfr[2 * j][0], bfr[2 * j][1], bfr[2 * j + 1][0], bfr[2 * j + 1][1],
                      bOct + kk + j * (16 * 80));
            #pragma unroll
            for (int mi = 0; mi < 4; mi++)
                #pragma unroll
                for (int ni = 0; ni < 8; ni++)
                    mma_fp16(acc[mi][ni], afr[mi], bfr[ni]);
        }
    }

    const int g = lane >> 2, tt = lane & 3;
    #pragma unroll
    for (int mi = 0; mi < 4; mi++) {
        #pragma unroll
        for (int ni = 0; ni < 8; ni++) {
            int row = m0 + wm + mi * 16 + g;
            int col = n0 + wn + ni * 8 + 2 * tt;
            if (col < N) {
                *(float2*)(Cb + (size_t)row * ldc + col) =
                    make_float2(acc[mi][ni][0], acc[mi][ni][1]);
                *(float2*)(Cb + (size_t)(row + 8) * ldc + col) =
                    make_float2(acc[mi][ni][2], acc[mi][ni][3]);
            }
        }
    }
}

// ---------------- depthwise conv (K=4) + SiLU + dt softplus ----------------
__global__ void conv_silu_dt(const float* __restrict__ conv_w,
                             const float* __restrict__ conv_b,
                             const float* __restrict__ dt_bias)
{
    const int bl = blockIdx.y;
    const int l = bl & (LL - 1);
    const int c = blockIdx.x * 256 + threadIdx.x;
    float acc = conv_b[c];
    #pragma unroll
    for (int k = 0; k < 4; k++) {
        int ls = l + k - 3;
        if (ls >= 0)
            acc += g_zxbcdt[(size_t)(bl + k - 3) * DIP + DINNER + c] * conv_w[c * 4 + k];
    }
    acc = acc / (1.f + __expf(-acc));
    g_xc[(size_t)bl * CONVD + c] = __uint_as_float(f2tf32(acc));   // tf32 for SSD path
    if (c >= DINNER)                                               // fp16 B|C for CBT GEMM
        g_bc_h[(size_t)bl * (2 * NS) + (c - DINNER)] = __float2half(acc);

    if (blockIdx.x == 0 && threadIdx.x < NH) {
        float x = g_zxbcdt[(size_t)bl * DIP + DINNER + CONVD + threadIdx.x] + dt_bias[threadIdx.x];
        float sp = (x > 20.f) ? x : log1pf(__expf(x));
        g_dt[(size_t)bl * NH + threadIdx.x] = sp;
    }
}

// ---------------- per-chunk inclusive cumsum of dA = dt * A ----------------
__global__ void chunk_cumsum(const float* __restrict__ A_log)
{
    const int idx = blockIdx.x;
    const int c = idx % NC;
    const int h = (idx / NC) % NH;
    const int b = idx / (NC * NH);
    const int s = threadIdx.x;
    __shared__ float sh[CS];
    float Ah = -__expf(A_log[h]);
    sh[s] = g_dt[((size_t)b * LL + c * CS + s) * NH + h] * Ah;
    __syncthreads();
    for (int off = 1; off < CS; off <<= 1) {
        float u = (s >= off) ? sh[s - off] : 0.f;
        __syncthreads();
        sh[s] += u;
        __syncthreads();
    }
    g_Acs[(size_t)idx * CS + s] = sh[s];
}

// ---------------- states (tf32 MMA, 256 threads — known-good) ----------------
__global__ __launch_bounds__(256, 2) void states_tf32()
{
    const int z = blockIdx.x;
    const int h = z % NH;
    const int bc = z / NH;
    const int c = bc % NC;
    const int b = bc / NC;
    __shared__ uint32_t Xs[16][132];
    __shared__ uint32_t Bs[16][132];
    __shared__ float ws[CS];
    const int t = threadIdx.x;
    {
        const float* acs = g_Acs + ((size_t)(b * NH + h) * NC + c) * CS;
        float last = acs[CS - 1];
        float dtv = g_dt[((size_t)b * LL + c * CS + t) * NH + h];
        ws[t] = dtv * __expf(last - acs[t]);
    }
    __syncthreads();
    const int lane = t & 31, w = t >> 5;
    const int wm = (w & 1) * 64, wn = (w >> 1) * 32;
    const int lr = t >> 4, lc = (t & 15) * 8;

    float acc[4][4][4];
    #pragma unroll
    for (int i = 0; i < 4; i++)
        #pragma unroll
        for (int j = 0; j < 4; j++)
            #pragma unroll
            for (int q = 0; q < 4; q++) acc[i][j][q] = 0.f;

    const float* xbase = g_xc + ((size_t)b * LL + c * CS) * CONVD + h * HP;
    const float* bbase = g_xc + ((size_t)b * LL + c * CS) * CONVD + DINNER;

    for (int k0 = 0; k0 < CS; k0 += 16) {
        const float wsv = ws[k0 + lr];
        const float* xr = xbase + (size_t)(k0 + lr) * CONVD + lc;
        const float* br = bbase + (size_t)(k0 + lr) * CONVD + lc;
        float4 x0 = *(const float4*)(xr), x1 = *(const float4*)(xr + 4);
        float4 b0 = *(const float4*)(br), b1 = *(const float4*)(br + 4);
        Xs[lr][lc+0]=f2tf32(x0.x*wsv); Xs[lr][lc+1]=f2tf32(x0.y*wsv);
        Xs[lr][lc+2]=f2tf32(x0.z*wsv); Xs[lr][lc+3]=f2tf32(x0.w*wsv);
        Xs[lr][lc+4]=f2tf32(x1.x*wsv); Xs[lr][lc+5]=f2tf32(x1.y*wsv);
        Xs[lr][lc+6]=f2tf32(x1.z*wsv); Xs[lr][lc+7]=f2tf32(x1.w*wsv);
        Bs[lr][lc+0]=__float_as_uint(b0.x); Bs[lr][lc+1]=__float_as_uint(b0.y);
        Bs[lr][lc+2]=__float_as_uint(b0.z); Bs[lr][lc+3]=__float_as_uint(b0.w);
        Bs[lr][lc+4]=__float_as_uint(b1.x); Bs[lr][lc+5]=__float_as_uint(b1.y);
        Bs[lr][lc+6]=__float_as_uint(b1.z); Bs[lr][lc+7]=__float_as_uint(b1.w);
        __syncthreads();
        #pragma unroll
        for (int kk = 0; kk < 16; kk += 8) {
            const int kcol = kk + (lane & 3);
            const int a = lane >> 2;
            uint32_t afr[4][4], bfr[4][2];
            #pragma unroll
            for (int mi = 0; mi < 4; mi++) {
                int r = wm + mi * 16 + a;
                afr[mi][0] = Xs[kcol][r];
                afr[mi][1] = Xs[kcol][r + 8];
                afr[mi][2] = Xs[kcol + 4][r];
                afr[mi][3] = Xs[kcol + 4][r + 8];
            }
            #pragma unroll
            for (int ni = 0; ni < 4; ni++) {
                int cn = wn + ni * 8 + a;
                bfr[ni][0] = Bs[kcol][cn];
                bfr[ni][1] = Bs[kcol + 4][cn];
            }
            #pragma unroll
            for (int mi = 0; mi < 4; mi++)
                #pragma unroll
                for (int ni = 0; ni < 4; ni++)
                    mma_tf32(acc[mi][ni], afr[mi], bfr[ni]);
        }
        __syncthreads();
    }

    float* sout = g_states + (size_t)z * HP * NS;
    const int g = lane >> 2, tt = lane & 3;
    #pragma unroll
    for (int mi = 0; mi < 4; mi++)
        #pragma unroll
        for (int ni = 0; ni < 4; ni++) {
            int row = wm + mi * 16 + g;
            int col = wn + ni * 8 + 2 * tt;
            *(float2*)(sout + (size_t)row * NS + col) =
                make_float2(acc[mi][ni][0], acc[mi][ni][1]);
            *(float2*)(sout + (size_t)(row + 8) * NS + col) =
                make_float2(acc[mi][ni][2], acc[mi][ni][3]);
        }
}

// ---------------- sequential scan over chunks (element-parallel) ----------------
__global__ void chunk_scan()
{
    const int bh = blockIdx.x;
    const int b = bh / NH, h = bh % NH;
    __shared__ float dec[NC];
    if (threadIdx.x < NC)
        dec[threadIdx.x] = __expf(g_Acs[((size_t)(b * NH + h) * NC + threadIdx.x) * CS + CS - 1]);
    __syncthreads();
    const int idx = blockIdx.y * 256 + threadIdx.x;
    float carry = 0.f;
    #pragma unroll
    for (int c = 0; c < NC; c++) {
        size_t base = ((size_t)((b * NC + c) * NH + h)) * HP * NS + idx;
        g_prev[base] = carry;
        carry = carry * dec[c] + g_states[base];
    }
}

// ---------------- Y (tf32 MMA, 256 threads, block-factorized decay exp) ----------------
__global__ __launch_bounds__(256, 2) void y_tf32(const float* __restrict__ Dp)
{
    const int z = blockIdx.y;
    const int h = z % NH;
    const int bc = z / NH;
    const int c = bc % NC;
    const int b = bc / NC;
    const int m0 = blockIdx.x * 128;

    __shared__ float sAcs[CS], sdt[CS];
    __shared__ float sh_e[16];
    __shared__ uint32_t As[128][20];
    __shared__ uint32_t Bt[16][132];
    __shared__ uint32_t B2[128][20];
    const int t = threadIdx.x;
    {
        const float* acs = g_Acs + ((size_t)(b * NH + h) * NC + c) * CS;
        sAcs[t] = acs[t];
        sdt[t] = g_dt[((size_t)b * LL + c * CS + t) * NH + h];
    }
    __syncthreads();

    const int lane = t & 31, w = t >> 5;
    const int wm = (w & 1) * 64, wn = (w >> 1) * 32;
    const int arow = t >> 1, ac8 = (t & 1) * 8;
    const int l_loc = m0 + arow;
    const float acs_l = sAcs[l_loc];
    const float eAl = __expf(acs_l);
    const int xr16 = t >> 4, xc8 = (t & 15) * 8;

    float acc[4][4][4];
    #pragma unroll
    for (int i = 0; i < 4; i++)
        #pragma unroll
        for (int j = 0; j < 4; j++)
            #pragma unroll
            for (int q = 0; q < 4; q++) acc[i][j][q] = 0.f;

    const float* cbt = g_CBT + (size_t)bc * CS * CS;
    const float* cbt_l = cbt + (size_t)l_loc * CS;
    const float* xrow = g_xc + ((size_t)b * LL + c * CS) * CONVD + h * HP;

    const int K1 = m0 + 128;
    for (int k0 = 0; k0 < K1; k0 += 16) {
        if (t < 16)
            sh_e[t] = __expf(sAcs[k0 + 15] - sAcs[k0 + t]) * sdt[k0 + t];
        __syncthreads();
        const float e_row = (l_loc >= k0) ? __expf(acs_l - sAcs[k0 + 15]) : 0.f;
        #pragma unroll
        for (int j = 0; j < 8; j++) {
            int s = k0 + ac8 + j;
            float v = 0.f;
            if (s <= l_loc)
                v = cbt_l[s] * e_row * sh_e[ac8 + j];
            As[arow][ac8 + j] = f2tf32(v);
        }
        const float* xr = xrow + (size_t)(k0 + xr16) * CONVD + xc8;
        float4 x0 = *(const float4*)(xr), x1 = *(const float4*)(xr + 4);
        Bt[xr16][xc8+0]=__float_as_uint(x0.x); Bt[xr16][xc8+1]=__float_as_uint(x0.y);
        Bt[xr16][xc8+2]=__float_as_uint(x0.z); Bt[xr16][xc8+3]=__float_as_uint(x0.w);
        Bt[xr16][xc8+4]=__float_as_uint(x1.x); Bt[xr16][xc8+5]=__float_as_uint(x1.y);
        Bt[xr16][xc8+6]=__float_as_uint(x1.z); Bt[xr16][xc8+7]=__float_as_uint(x1.w);
        __syncthreads();
        #pragma unroll
        for (int kk = 0; kk < 16; kk += 8) {
            const int kcol = kk + (lane & 3);
            const int a = lane >> 2;
            uint32_t afr[4][4], bfr[4][2];
            #pragma unroll
            for (int mi = 0; mi < 4; mi++) {
                int r = wm + mi * 16 + a;
                afr[mi][0] = As[r][kcol];
                afr[mi][1] = As[r + 8][kcol];
                afr[mi][2] = As[r][kcol + 4];
                afr[mi][3] = As[r + 8][kcol + 4];
            }
            #pragma unroll
            for (int ni = 0; ni < 4; ni++) {
                int cn = wn + ni * 8 + a;
                bfr[ni][0] = Bt[kcol][cn];
                bfr[ni][1] = Bt[kcol + 4][cn];
            }
            #pragma unroll
            for (int mi = 0; mi < 4; mi++)
                #pragma unroll
                for (int ni = 0; ni < 4; ni++)
                    mma_tf32(acc[mi][ni], afr[mi], bfr[ni]);
        }
        __syncthreads();
    }

    const float* crow = g_xc + ((size_t)b * LL + c * CS) * CONVD + DINNER + NS;
    const float* prow = g_prev + (size_t)z * HP * NS;
    for (int k0 = 0; k0 < NS; k0 += 16) {
        const float* cr = crow + (size_t)l_loc * CONVD + k0 + ac8;
        float4 c0 = *(const float4*)(cr), c1 = *(const float4*)(cr + 4);
        As[arow][ac8+0]=f2tf32(c0.x*eAl); As[arow][ac8+1]=f2tf32(c0.y*eAl);
        As[arow][ac8+2]=f2tf32(c0.z*eAl); As[arow][ac8+3]=f2tf32(c0.w*eAl);
        As[arow][ac8+4]=f2tf32(c1.x*eAl); As[arow][ac8+5]=f2tf32(c1.y*eAl);
        As[arow][ac8+6]=f2tf32(c1.z*eAl); As[arow][ac8+7]=f2tf32(c1.w*eAl);
        const float* pr = prow + (size_t)arow * NS + k0 + ac8;
        float4 p0 = *(const float4*)(pr), p1 = *(const float4*)(pr + 4);
        B2[arow][ac8+0]=f2tf32(p0.x); B2[arow][ac8+1]=f2tf32(p0.y);
        B2[arow][ac8+2]=f2tf32(p0.z); B2[arow][ac8+3]=f2tf32(p0.w);
        B2[arow][ac8+4]=f2tf32(p1.x); B2[arow][ac8+5]=f2tf32(p1.y);
        B2[arow][ac8+6]=f2tf32(p1.z); B2[arow][ac8+7]=f2tf32(p1.w);
        __syncthreads();
        #pragma unroll
        for (int kk = 0; kk < 16; kk += 8) {
            const int kcol = kk + (lane & 3);
            const int a = lane >> 2;
            uint32_t afr[4][4], bfr[4][2];
            #pragma unroll
            for (int mi = 0; mi < 4; mi++) {
                int r = wm + mi * 16 + a;
                afr[mi][0] = As[r][kcol];
                afr[mi][1] = As[r + 8][kcol];
                afr[mi][2] = As[r][kcol + 4];
                afr[mi][3] = As[r + 8][kcol + 4];
            }
            #pragma unroll
            for (int ni = 0; ni < 4; ni++) {
                int cn = wn + ni * 8 + a;
                bfr[ni][0] = B2[cn][kcol];
                bfr[ni][1] = B2[cn][kcol + 4];
            }
            #pragma unroll
            for (int mi = 0; mi < 4; mi++)
                #pragma unroll
                for (int ni = 0; ni < 4; ni++)
                    mma_tf32(acc[mi][ni], afr[mi], bfr[ni]);
        }
        __syncthreads();
    }

    const float Dh = Dp[h];
    const int g = lane >> 2, tt = lane & 3;
    #pragma unroll
    for (int mi = 0; mi < 4; mi++)
        #pragma unroll
        for (int ni = 0; ni < 4; ni++) {
            int l0 = m0 + wm + mi * 16 + g;
            int p = wn + ni * 8 + 2 * tt;
            float2 xv0 = *(const float2*)(xrow + (size_t)l0 * CONVD + p);
            float2 xv1 = *(const float2*)(xrow + (size_t)(l0 + 8) * CONVD + p);
            float* o0 = g_y + ((size_t)b * LL + c * CS + l0) * DINNER + h * HP + p;
            float* o1 = g_y + ((size_t)b * LL + c * CS + l0 + 8) * DINNER + h * HP + p;
            *(float2*)o0 = make_float2(acc[mi][ni][0] + Dh * xv0.x,
                                       acc[mi][ni][1] + Dh * xv0.y);
            *(float2*)o1 = make_float2(acc[mi][ni][2] + Dh * xv1.x,
                                       acc[mi][ni][3] + Dh * xv1.y);
        }
}

// ---------------- gating (silu(z)) + RMS norm -> fp16 ----------------
__global__ void gate_norm(const float* __restrict__ norm_w)
{
    const int row = blockIdx.x;
    const int t = threadIdx.x;
    __shared__ float red[256];
    float vals[8];
    float local = 0.f;
    const float* yrow = g_y + (size_t)row * DINNER;
    const float* zrow = g_zxbcdt + (size_t)row * DIP;
    #pragma unroll
    for (int e = 0; e < 8; e++) {
        int i = e * 256 + t;
        float zv = zrow[i];
        float gv = yrow[i] * zv / (1.f + __expf(-zv));
        vals[e] = gv;
        local += gv * gv;
    }
    red[t] = local;
    __syncthreads();
    for (int off = 128; off > 0; off >>= 1) {
        if (t < off) red[t] += red[t + off];
        __syncthreads();
    }
    float scale = rsqrtf(red[0] / (float)DINNER + 1e-5f);
    __half* out = g_yg_h + (size_t)row * DINNER;
    #pragma unroll
    for (int e = 0; e < 8; e++) {
        int i = e * 256 + t;
        out[i] = __float2half(vals[e] * scale * norm_w[i]);
    }
}

// ---------------- host launcher ----------------
extern "C" void kernel_launch(void* const* d_in, const int* in_sizes, int n_in,
                              void* d_out, int out_size)
{
    const float* u       = (const float*)d_in[0];
    const float* W_in    = (const float*)d_in[1];
    const float* conv_w  = (const float*)d_in[2];
    const float* conv_b  = (const float*)d_in[3];
    const float* dt_bias = (const float*)d_in[4];
    const float* A_log   = (const float*)d_in[5];
    const float* Dp      = (const float*)d_in[6];
    const float* norm_w  = (const float*)d_in[7];
    const float* W_out   = (const float*)d_in[8];
    float* out = (float*)d_out;

    float *zx, *xc, *cbt, *y;
    __half *uh, *wih, *woh, *bch, *ygh;
    cudaGetSymbolAddress((void**)&zx,  g_zxbcdt);
    cudaGetSymbolAddress((void**)&xc,  g_xc);
    cudaGetSymbolAddress((void**)&cbt, g_CBT);
    cudaGetSymbolAddress((void**)&y,   g_y);
    cudaGetSymbolAddress((void**)&uh,  g_u_h);
    cudaGetSymbolAddress((void**)&wih, g_Win_h);
    cudaGetSymbolAddress((void**)&woh, g_Wout_h);
    cudaGetSymbolAddress((void**)&bch, g_bc_h);
    cudaGetSymbolAddress((void**)&ygh, g_yg_h);

    const int gemmSmem = GSTG * (A_STG_B + B_STG_B);  // 92160 B
    cudaFuncSetAttribute(gemm_fp16_nt,
                         cudaFuncAttributeMaxDynamicSharedMemorySize, gemmSmem);

    // 0) convert dense-GEMM inputs to fp16
    {
        int nu = BB * LL * DM;
        round_fp16<<<(nu / 4 + 255) / 256, 256>>>(u, uh, nu);
        int nwi = DIP * DM;
        round_fp16<<<(nwi / 4 + 255) / 256, 256>>>(W_in, wih, nwi);
        int nwo = DM * DINNER;
        round_fp16<<<(nwo / 4 + 255) / 256, 256>>>(W_out, woh, nwo);
    }

    // 1) in-proj: zxbcdt = u_h @ W_in_h^T   (fp16 MMA, K=1024)
    gemm_fp16_nt<<<dim3((DIP + 127) / 128, (BB * LL) / 256, 1), 256, gemmSmem>>>(
        uh, DM, 0, wih, DM, 0, zx, DIP, 0, DIP, DM);

    // 2) conv + silu + dt softplus (tf32 g_xc + fp16 B|C mirror)
    conv_silu_dt<<<dim3(CONVD / 256, BB * LL), 256>>>(conv_w, conv_b, dt_bias);

    // 3) per-chunk cumsum of dA
    chunk_cumsum<<<BB * NH * NC, CS>>>(A_log);

    // 4) CBT[b,c] = C @ B^T  (fp16 MMA, M=256, N=256, K=128)
    gemm_fp16_nt<<<dim3(2, 1, BB * NC), 256, gemmSmem>>>(
        bch + NS, 2 * NS, (long long)CS * 2 * NS,
        bch,      2 * NS, (long long)CS * 2 * NS,
        cbt, CS, (long long)CS * CS,
        CS, NS);

    // 5) per-chunk states (tf32 MMA)
    states_tf32<<<BB * NC * NH, 256>>>();

    // 6) inter-chunk scan (element-parallel)
    chunk_scan<<<dim3(BB * NH, (HP * NS) / 256), 256>>>();

    // 7) Y = diag + off + D*x (tf32 MMA)
    y_tf32<<<dim3(2, BB * NC * NH), 256>>>(Dp);

    // 8) gating + RMS norm (fp16 output)
    gate_norm<<<BB * LL, 256>>>(norm_w);

    // 9) out-proj: out = yg_h @ W_out_h^T   (fp16 MMA, K=2048)
    gemm_fp16_nt<<<dim3(DM / 128, (BB * LL) / 256, 1), 256, gemmSmem>>>(
        ygh, DINNER, 0, woh, DINNER, 0, out, DM, 0, DM, DINNER);
}

// round 13
// speedup vs baseline: 1.6697x; 1.0813x over previous
#include <cuda_runtime.h>
#include <cuda_fp16.h>
#include <math.h>
#include <stdint.h>

// ---------------- problem constants ----------------
#define BB 4
#define LL 2048
#define DM 1024
#define DIP 4368          // 2*D_INNER + 2*D_STATE + NHEADS
#define DINNER 2048
#define CONVD 2304        // D_INNER + 2*D_STATE
#define NH 16
#define HP 128            // head dim
#define NS 128            // state dim
#define CS 256            // chunk size
#define NC 8              // chunks per sequence

// ---------------- scratch (device globals; no allocation) ----------------
__device__ float g_zxbcdt[(size_t)BB * LL * DIP];     // in-proj output
__device__ float g_xc[(size_t)BB * LL * CONVD];       // conv+silu output (tf32-rounded)
__device__ float g_dt[(size_t)BB * LL * NH];          // softplus(dt)
__device__ float g_Acs[(size_t)BB * NH * NC * CS];    // per-chunk inclusive cumsum of dA
__device__ float g_CBT[(size_t)BB * NC * CS * CS];    // C @ B^T per (b,chunk)
__device__ float g_states[(size_t)BB * NC * NH * HP * NS];
__device__ float g_prev[(size_t)BB * NC * NH * HP * NS];
__device__ float g_y[(size_t)BB * LL * DINNER];       // pre-out-proj activations
__device__ __half g_u_h[(size_t)BB * LL * DM];        // fp16 u
__device__ __half g_Win_h[(size_t)DIP * DM];          // fp16 W_in
__device__ __half g_Wout_h[(size_t)DM * DINNER];      // fp16 W_out
__device__ __half g_bc_h[(size_t)BB * LL * 2 * NS];   // fp16 B|C (conv output cols)
__device__ __half g_yg_h[(size_t)BB * LL * DINNER];   // fp16 gated+normed y

// ---------------- helpers ----------------
__device__ __forceinline__ uint32_t f2tf32(float f) {
    uint32_t r;
    asm("cvt.rna.tf32.f32 %0, %1;" : "=r"(r) : "f"(f));
    return r;
}

__device__ __forceinline__ void mma_fp16(float c[4], const uint32_t a[4], const uint32_t b[2]) {
    asm volatile(
        "mma.sync.aligned.m16n8k16.row.col.f32.f16.f16.f32 "
        "{%0,%1,%2,%3}, {%4,%5,%6,%7}, {%8,%9}, {%0,%1,%2,%3};"
        : "+f"(c[0]), "+f"(c[1]), "+f"(c[2]), "+f"(c[3])
        : "r"(a[0]), "r"(a[1]), "r"(a[2]), "r"(a[3]), "r"(b[0]), "r"(b[1]));
}

__device__ __forceinline__ void ldsm4(uint32_t& r0, uint32_t& r1, uint32_t& r2, uint32_t& r3,
                                      uint32_t addr) {
    asm volatile("ldmatrix.sync.aligned.m8n8.x4.shared.b16 {%0,%1,%2,%3}, [%4];"
                 : "=r"(r0), "=r"(r1), "=r"(r2), "=r"(r3) : "r"(addr));
}

__device__ __forceinline__ void ldsm4t(uint32_t& r0, uint32_t& r1, uint32_t& r2, uint32_t& r3,
                                       uint32_t addr) {
    asm volatile("ldmatrix.sync.aligned.m8n8.x4.trans.shared.b16 {%0,%1,%2,%3}, [%4];"
                 : "=r"(r0), "=r"(r1), "=r"(r2), "=r"(r3) : "r"(addr));
}

__device__ __forceinline__ void cp16(uint32_t dst, const void* src, bool ok) {
    int sz = ok ? 16 : 0;
    asm volatile("cp.async.ca.shared.global [%0], [%1], 16, %2;\n"
                 :: "r"(dst), "l"(src), "r"(sz));
}
#define CP_COMMIT() asm volatile("cp.async.commit_group;\n")
#define CP_WAIT1()  asm volatile("cp.async.wait_group 1;\n" ::: "memory")

// ---------------- elementwise fp32 -> fp16 ----------------
__global__ void round_fp16(const float* __restrict__ s, __half* __restrict__ d, int n)
{
    int i = (blockIdx.x * 256 + threadIdx.x) * 4;
    if (i >= n) return;
    float4 v = *(const float4*)(s + i);
    *(__half2*)(d + i)     = __floats2half2_rn(v.x, v.y);
    *(__half2*)(d + i + 2) = __floats2half2_rn(v.z, v.w);
}

// ---------------- fp16 NT GEMM: 256 threads, 8 warps, 256x128 CTA tile ----------------
// (round-12 known-good, unchanged)
#define GSTG 3
#define A_STG_B (256 * 80)
#define B_STG_B (128 * 80)
#define GB_OFF (GSTG * A_STG_B)
__global__ __launch_bounds__(256, 1) void gemm_fp16_nt(
    const __half* __restrict__ A, int lda, long long sA,
    const __half* __restrict__ B, int ldb, long long sB,
    float* __restrict__ C, int ldc, long long sC,
    int N, int K)
{
    extern __shared__ char smraw[];
    const __half* Ab = A + (size_t)blockIdx.z * sA;
    const __half* Bb = B + (size_t)blockIdx.z * sB;
    float* Cb = C + (size_t)blockIdx.z * sC;
    const int m0 = blockIdx.y * 256, n0 = blockIdx.x * 128;
    const int t = threadIdx.x;
    const int lane = t & 31, w = t >> 5;
    const int wm = (w >> 1) * 64, wn = (w & 1) * 64;

    const bool bldr = (t < 128);
    const bool bok = bldr && ((n0 + t) < N);
    const __half* aS = Ab + (size_t)(m0 + t) * lda;
    const __half* bS = Bb + (size_t)(bok ? n0 + t : 0) * ldb;
    const uint32_t smBase = (uint32_t)__cvta_generic_to_shared(smraw);
    const uint32_t dA = smBase + t * 80;
    const uint32_t dB = smBase + GB_OFF + t * 80;

    const uint32_t aFragOff = (uint32_t)((wm + (lane & 15)) * 80 + (lane >> 4) * 16);
    const uint32_t bFragOff = (uint32_t)((wn + ((lane >> 4) << 3) + (lane & 7)) * 80
                                         + ((lane >> 3) & 1) * 16);

    float acc[4][8][4];
    #pragma unroll
    for (int i = 0; i < 4; i++)
        #pragma unroll
        for (int j = 0; j < 8; j++)
            #pragma unroll
            for (int q = 0; q < 4; q++) acc[i][j][q] = 0.f;

    const int nIter = K >> 5;
    #pragma unroll
    for (int s = 0; s < GSTG - 1; s++) {
        const uint32_t offA = s * A_STG_B;
        const uint32_t offB = s * B_STG_B;
        const int k0 = s << 5;
        cp16(dA + offA,      aS + k0,      true);
        cp16(dA + offA + 16, aS + k0 + 8,  true);
        cp16(dA + offA + 32, aS + k0 + 16, true);
        cp16(dA + offA + 48, aS + k0 + 24, true);
        if (bldr) {
            cp16(dB + offB,      bS + k0,      bok);
            cp16(dB + offB + 16, bS + k0 + 8,  bok);
            cp16(dB + offB + 32, bS + k0 + 16, bok);
            cp16(dB + offB + 48, bS + k0 + 24, bok);
        }
        CP_COMMIT();
    }

    for (int it = 0; it < nIter; it++) {
        CP_WAIT1();
        __syncthreads();
        const int pf = it + GSTG - 1;
        if (pf < nIter) {
            const uint32_t offA = (pf % GSTG) * A_STG_B;
            const uint32_t offB = (pf % GSTG) * B_STG_B;
            const int k0 = pf << 5;
            cp16(dA + offA,      aS + k0,      true);
            cp16(dA + offA + 16, aS + k0 + 8,  true);
            cp16(dA + offA + 32, aS + k0 + 16, true);
            cp16(dA + offA + 48, aS + k0 + 24, true);
            if (bldr) {
                cp16(dB + offB,      bS + k0,      bok);
                cp16(dB + offB + 16, bS + k0 + 8,  bok);
                cp16(dB + offB + 32, bS + k0 + 16, bok);
                cp16(dB + offB + 48, bS + k0 + 24, bok);
            }
        }
        CP_COMMIT();

        const uint32_t aOct = smBase + (it % GSTG) * A_STG_B + aFragOff;
        const uint32_t bOct = smBase + GB_OFF + (it % GSTG) * B_STG_B + bFragOff;
        #pragma unroll
        for (int kk = 0; kk < 64; kk += 32) {
            uint32_t afr[4][4], bfr[8][2];
            #pragma unroll
            for (int mi = 0; mi < 4; mi++)
                ldsm4(afr[mi][0], afr[mi][1], afr[mi][2], afr[mi][3],
                      aOct + kk + mi * (16 * 80));
            #pragma unroll
            for (int j = 0; j < 4; j++)
                ldsm4(bfr[2 * j][0], bfr[2 * j][1], bfr[2 * j + 1][0], bfr[2 * j + 1][1],
                      bOct + kk + j * (16 * 80));
            #pragma unroll
            for (int mi = 0; mi < 4; mi++)
                #pragma unroll
                for (int ni = 0; ni < 8; ni++)
                    mma_fp16(acc[mi][ni], afr[mi], bfr[ni]);
        }
    }

    const int g = lane >> 2, tt = lane & 3;
    #pragma unroll
    for (int mi = 0; mi < 4; mi++) {
        #pragma unroll
        for (int ni = 0; ni < 8; ni++) {
            int row = m0 + wm + mi * 16 + g;
            int col = n0 + wn + ni * 8 + 2 * tt;
            if (col < N) {
                *(float2*)(Cb + (size_t)row * ldc + col) =
                    make_float2(acc[mi][ni][0], acc[mi][ni][1]);
                *(float2*)(Cb + (size_t)(row + 8) * ldc + col) =
                    make_float2(acc[mi][ni][2], acc[mi][ni][3]);
            }
        }
    }
}

// ---------------- depthwise conv (K=4) + SiLU + dt softplus ----------------
__global__ void conv_silu_dt(const float* __restrict__ conv_w,
                             const float* __restrict__ conv_b,
                             const float* __restrict__ dt_bias)
{
    const int bl = blockIdx.y;
    const int l = bl & (LL - 1);
    const int c = blockIdx.x * 256 + threadIdx.x;
    float acc = conv_b[c];
    #pragma unroll
    for (int k = 0; k < 4; k++) {
        int ls = l + k - 3;
        if (ls >= 0)
            acc += g_zxbcdt[(size_t)(bl + k - 3) * DIP + DINNER + c] * conv_w[c * 4 + k];
    }
    acc = acc / (1.f + __expf(-acc));
    g_xc[(size_t)bl * CONVD + c] = __uint_as_float(f2tf32(acc));
    if (c >= DINNER)
        g_bc_h[(size_t)bl * (2 * NS) + (c - DINNER)] = __float2half(acc);

    if (blockIdx.x == 0 && threadIdx.x < NH) {
        float x = g_zxbcdt[(size_t)bl * DIP + DINNER + CONVD + threadIdx.x] + dt_bias[threadIdx.x];
        float sp = (x > 20.f) ? x : log1pf(__expf(x));
        g_dt[(size_t)bl * NH + threadIdx.x] = sp;
    }
}

// ---------------- per-chunk inclusive cumsum of dA = dt * A ----------------
__global__ void chunk_cumsum(const float* __restrict__ A_log)
{
    const int idx = blockIdx.x;
    const int c = idx % NC;
    const int h = (idx / NC) % NH;
    const int b = idx / (NC * NH);
    const int s = threadIdx.x;
    __shared__ float sh[CS];
    float Ah = -__expf(A_log[h]);
    sh[s] = g_dt[((size_t)b * LL + c * CS + s) * NH + h] * Ah;
    __syncthreads();
    for (int off = 1; off < CS; off <<= 1) {
        float u = (s >= off) ? sh[s - off] : 0.f;
        __syncthreads();
        sh[s] += u;
        __syncthreads();
    }
    g_Acs[(size_t)idx * CS + s] = sh[s];
}

// ---------------- states (fp16 MMA, 256 threads, trans ldmatrix) ----------------
// states[p,n] = sum_s ws[s]*x[s,p]*B[s,n]; k-major smem tiles [16 k][136 halves].
#define KM_STRIDE 272   // bytes per k-row (128 halves + 8 pad)
__global__ __launch_bounds__(256, 2) void states_fp16()
{
    const int z = blockIdx.x;
    const int h = z % NH;
    const int bc = z / NH;
    const int c = bc % NC;
    const int b = bc / NC;
    __shared__ __half Xs[16][136];
    __shared__ __half Bs[16][136];
    __shared__ float ws[CS];
    const int t = threadIdx.x;
    {
        const float* acs = g_Acs + ((size_t)(b * NH + h) * NC + c) * CS;
        float last = acs[CS - 1];
        float dtv = g_dt[((size_t)b * LL + c * CS + t) * NH + h];
        ws[t] = dtv * __expf(last - acs[t]);
    }
    __syncthreads();
    const int lane = t & 31, w = t >> 5;
    const int wm = (w & 1) * 64, wn = (w >> 1) * 32;
    const int lr = t >> 4, lc = (t & 15) * 8;
    const uint32_t smX = (uint32_t)__cvta_generic_to_shared(&Xs[0][0]);
    const uint32_t smB = (uint32_t)__cvta_generic_to_shared(&Bs[0][0]);
    // trans-ldmatrix lane addressing (A: m-tiles; B: n-tile pairs)
    const uint32_t aRowOff = (uint32_t)(((lane & 7) + ((lane >> 4) << 3)) * KM_STRIDE
                                        + ((lane >> 3) & 1) * 16);
    const uint32_t bRowOff = (uint32_t)(((lane & 7) + ((lane >> 3) & 1) * 8) * KM_STRIDE
                                        + ((lane >> 4) << 4));

    float acc[4][4][4];
    #pragma unroll
    for (int i = 0; i < 4; i++)
        #pragma unroll
        for (int j = 0; j < 4; j++)
            #pragma unroll
            for (int q = 0; q < 4; q++) acc[i][j][q] = 0.f;

    const float* xbase = g_xc + ((size_t)b * LL + c * CS) * CONVD + h * HP;
    const float* bbase = g_xc + ((size_t)b * LL + c * CS) * CONVD + DINNER;

    for (int k0 = 0; k0 < CS; k0 += 16) {
        const float wsv = ws[k0 + lr];
        const float* xr = xbase + (size_t)(k0 + lr) * CONVD + lc;
        const float* br = bbase + (size_t)(k0 + lr) * CONVD + lc;
        float4 x0 = *(const float4*)(xr), x1 = *(const float4*)(xr + 4);
        float4 b0 = *(const float4*)(br), b1 = *(const float4*)(br + 4);
        *(__half2*)&Xs[lr][lc + 0] = __floats2half2_rn(x0.x * wsv, x0.y * wsv);
        *(__half2*)&Xs[lr][lc + 2] = __floats2half2_rn(x0.z * wsv, x0.w * wsv);
        *(__half2*)&Xs[lr][lc + 4] = __floats2half2_rn(x1.x * wsv, x1.y * wsv);
        *(__half2*)&Xs[lr][lc + 6] = __floats2half2_rn(x1.z * wsv, x1.w * wsv);
        *(__half2*)&Bs[lr][lc + 0] = __floats2half2_rn(b0.x, b0.y);
        *(__half2*)&Bs[lr][lc + 2] = __floats2half2_rn(b0.z, b0.w);
        *(__half2*)&Bs[lr][lc + 4] = __floats2half2_rn(b1.x, b1.y);
        *(__half2*)&Bs[lr][lc + 6] = __floats2half2_rn(b1.z, b1.w);
        __syncthreads();
        uint32_t afr[4][4], bfr[4][2];
        #pragma unroll
        for (int mi = 0; mi < 4; mi++)
            ldsm4t(afr[mi][0], afr[mi][1], afr[mi][2], afr[mi][3],
                   smX + aRowOff + (wm + mi * 16) * 2);
        #pragma unroll
        for (int np = 0; np < 2; np++)
            ldsm4t(bfr[2 * np][0], bfr[2 * np][1], bfr[2 * np + 1][0], bfr[2 * np + 1][1],
                   smB + bRowOff + (wn + np * 16) * 2);
        #pragma unroll
        for (int mi = 0; mi < 4; mi++)
            #pragma unroll
            for (int ni = 0; ni < 4; ni++)
                mma_fp16(acc[mi][ni], afr[mi], bfr[ni]);
        __syncthreads();
    }

    float* sout = g_states + (size_t)z * HP * NS;
    const int g = lane >> 2, tt = lane & 3;
    #pragma unroll
    for (int mi = 0; mi < 4; mi++)
        #pragma unroll
        for (int ni = 0; ni < 4; ni++) {
            int row = wm + mi * 16 + g;
            int col = wn + ni * 8 + 2 * tt;
            *(float2*)(sout + (size_t)row * NS + col) =
                make_float2(acc[mi][ni][0], acc[mi][ni][1]);
            *(float2*)(sout + (size_t)(row + 8) * NS + col) =
                make_float2(acc[mi][ni][2], acc[mi][ni][3]);
        }
}

// ---------------- sequential scan over chunks (element-parallel) ----------------
__global__ void chunk_scan()
{
    const int bh = blockIdx.x;
    const int b = bh / NH, h = bh % NH;
    __shared__ float dec[NC];
    if (threadIdx.x < NC)
        dec[threadIdx.x] = __expf(g_Acs[((size_t)(b * NH + h) * NC + threadIdx.x) * CS + CS - 1]);
    __syncthreads();
    const int idx = blockIdx.y * 256 + threadIdx.x;
    float carry = 0.f;
    #pragma unroll
    for (int c = 0; c < NC; c++) {
        size_t base = ((size_t)((b * NC + c) * NH + h)) * HP * NS + idx;
        g_prev[base] = carry;
        carry = carry * dec[c] + g_states[base];
    }
}

// ---------------- Y (fp16 MMA, 256 threads) ----------------
// phase1: A = masked(CBT*decay*dt) row-major fp16 [128][24]; B = x k-major (trans).
// phase2: A = C*eAl row-major; B = prev row-major (normal ldmatrix).
#define RM_STRIDE 48    // bytes per row (16 halves + 8 pad)
__global__ __launch_bounds__(256, 2) void y_fp16(const float* __restrict__ Dp)
{
    const int z = blockIdx.y;
    const int h = z % NH;
    const int bc = z / NH;
    const int c = bc % NC;
    const int b = bc / NC;
    const int m0 = blockIdx.x * 128;

    __shared__ float sAcs[CS], sdt[CS];
    __shared__ float sh_e[16];
    __shared__ __half As[128][24];
    __shared__ __half Bt[16][136];
    __shared__ __half B2[128][24];
    const int t = threadIdx.x;
    {
        const float* acs = g_Acs + ((size_t)(b * NH + h) * NC + c) * CS;
        sAcs[t] = acs[t];
        sdt[t] = g_dt[((size_t)b * LL + c * CS + t) * NH + h];
    }
    __syncthreads();

    const int lane = t & 31, w = t >> 5;
    const int wm = (w & 1) * 64, wn = (w >> 1) * 32;
    const int arow = t >> 1, ac8 = (t & 1) * 8;
    const int l_loc = m0 + arow;
    const float acs_l = sAcs[l_loc];
    const float eAl = __expf(acs_l);
    const int xr16 = t >> 4, xc8 = (t & 15) * 8;

    const uint32_t smA  = (uint32_t)__cvta_generic_to_shared(&As[0][0]);
    const uint32_t smBt = (uint32_t)__cvta_generic_to_shared(&Bt[0][0]);
    const uint32_t smB2 = (uint32_t)__cvta_generic_to_shared(&B2[0][0]);
    const uint32_t aFrag  = (uint32_t)((wm + (lane & 15)) * RM_STRIDE + (lane >> 4) * 16);
    const uint32_t btFrag = (uint32_t)(((lane & 7) + ((lane >> 3) & 1) * 8) * KM_STRIDE
                                       + ((lane >> 4) << 4));
    const uint32_t b2Frag = (uint32_t)((wn + ((lane >> 4) << 3) + (lane & 7)) * RM_STRIDE
                                       + ((lane >> 3) & 1) * 16);

    float acc[4][4][4];
    #pragma unroll
    for (int i = 0; i < 4; i++)
        #pragma unroll
        for (int j = 0; j < 4; j++)
            #pragma unroll
            for (int q = 0; q < 4; q++) acc[i][j][q] = 0.f;

    const float* cbt_l = g_CBT + (size_t)bc * CS * CS + (size_t)l_loc * CS;
    const float* xrow = g_xc + ((size_t)b * LL + c * CS) * CONVD + h * HP;

    // ---- phase 1: intra-chunk, K = m0+128 (factorized decay exp) ----
    const int K1 = m0 + 128;
    for (int k0 = 0; k0 < K1; k0 += 16) {
        if (t < 16)
            sh_e[t] = __expf(sAcs[k0 + 15] - sAcs[k0 + t]) * sdt[k0 + t];
        __syncthreads();
        const float e_row = (l_loc >= k0) ? __expf(acs_l - sAcs[k0 + 15]) : 0.f;
        #pragma unroll
        for (int j = 0; j < 8; j += 2) {
            int s = k0 + ac8 + j;
            float v0 = (s     <= l_loc) ? cbt_l[s]     * e_row * sh_e[ac8 + j]     : 0.f;
            float v1 = (s + 1 <= l_loc) ? cbt_l[s + 1] * e_row * sh_e[ac8 + j + 1] : 0.f;
            *(__half2*)&As[arow][ac8 + j] = __floats2half2_rn(v0, v1);
        }
        const float* xr = xrow + (size_t)(k0 + xr16) * CONVD + xc8;
        float4 x0 = *(const float4*)(xr), x1 = *(const float4*)(xr + 4);
        *(__half2*)&Bt[xr16][xc8 + 0] = __floats2half2_rn(x0.x, x0.y);
        *(__half2*)&Bt[xr16][xc8 + 2] = __floats2half2_rn(x0.z, x0.w);
        *(__half2*)&Bt[xr16][xc8 + 4] = __floats2half2_rn(x1.x, x1.y);
        *(__half2*)&Bt[xr16][xc8 + 6] = __floats2half2_rn(x1.z, x1.w);
        __syncthreads();
        uint32_t afr[4][4], bfr[4][2];
        #pragma unroll
        for (int mi = 0; mi < 4; mi++)
            ldsm4(afr[mi][0], afr[mi][1], afr[mi][2], afr[mi][3],
                  smA + aFrag + mi * (16 * RM_STRIDE));
        #pragma unroll
        for (int np = 0; np < 2; np++)
            ldsm4t(bfr[2 * np][0], bfr[2 * np][1], bfr[2 * np + 1][0], bfr[2 * np + 1][1],
                   smBt + btFrag + (wn + np * 16) * 2);
        #pragma unroll
        for (int mi = 0; mi < 4; mi++)
            #pragma unroll
            for (int ni = 0; ni < 4; ni++)
                mma_fp16(acc[mi][ni], afr[mi], bfr[ni]);
        __syncthreads();
    }

    // ---- phase 2: inter-chunk, K = NS = 128 ----
    const float* crow = g_xc + ((size_t)b * LL + c * CS) * CONVD + DINNER + NS;
    const float* prow = g_prev + (size_t)z * HP * NS;
    for (int k0 = 0; k0 < NS; k0 += 16) {
        const float* cr = crow + (size_t)l_loc * CONVD + k0 + ac8;
        float4 c0 = *(const float4*)(cr), c1 = *(const float4*)(cr + 4);
        *(__half2*)&As[arow][ac8 + 0] = __floats2half2_rn(c0.x * eAl, c0.y * eAl);
        *(__half2*)&As[arow][ac8 + 2] = __floats2half2_rn(c0.z * eAl, c0.w * eAl);
        *(__half2*)&As[arow][ac8 + 4] = __floats2half2_rn(c1.x * eAl, c1.y * eAl);
        *(__half2*)&As[arow][ac8 + 6] = __floats2half2_rn(c1.z * eAl, c1.w * eAl);
        const float* pr = prow + (size_t)arow * NS + k0 + ac8;
        float4 p0 = *(const float4*)(pr), p1 = *(const float4*)(pr + 4);
        *(__half2*)&B2[arow][ac8 + 0] = __floats2half2_rn(p0.x, p0.y);
        *(__half2*)&B2[arow][ac8 + 2] = __floats2half2_rn(p0.z, p0.w);
        *(__half2*)&B2[arow][ac8 + 4] = __floats2half2_rn(p1.x, p1.y);
        *(__half2*)&B2[arow][ac8 + 6] = __floats2half2_rn(p1.z, p1.w);
        __syncthreads();
        uint32_t afr[4][4], bfr[4][2];
        #pragma unroll
        for (int mi = 0; mi < 4; mi++)
            ldsm4(afr[mi][0], afr[mi][1], afr[mi][2], afr[mi][3],
                  smA + aFrag + mi * (16 * RM_STRIDE));
        #pragma unroll
        for (int np = 0; np < 2; np++)
            ldsm4(bfr[2 * np][0], bfr[2 * np][1], bfr[2 * np + 1][0], bfr[2 * np + 1][1],
                  smB2 + b2Frag + np * (16 * RM_STRIDE));
        #pragma unroll
        for (int mi = 0; mi < 4; mi++)
            #pragma unroll
            for (int ni = 0; ni < 4; ni++)
                mma_fp16(acc[mi][ni], afr[mi], bfr[ni]);
        __syncthreads();
    }

    const float Dh = Dp[h];
    const int g = lane >> 2, tt = lane & 3;
    #pragma unroll
    for (int mi = 0; mi < 4; mi++)
        #pragma unroll
        for (int ni = 0; ni < 4; ni++) {
            int l0 = m0 + wm + mi * 16 + g;
            int p = wn + ni * 8 + 2 * tt;
            float2 xv0 = *(const float2*)(xrow + (size_t)l0 * CONVD + p);
            float2 xv1 = *(const float2*)(xrow + (size_t)(l0 + 8) * CONVD + p);
            float* o0 = g_y + ((size_t)b * LL + c * CS + l0) * DINNER + h * HP + p;
            float* o1 = g_y + ((size_t)b * LL + c * CS + l0 + 8) * DINNER + h * HP + p;
            *(float2*)o0 = make_float2(acc[mi][ni][0] + Dh * xv0.x,
                                       acc[mi][ni][1] + Dh * xv0.y);
            *(float2*)o1 = make_float2(acc[mi][ni][2] + Dh * xv1.x,
                                       acc[mi][ni][3] + Dh * xv1.y);
        }
}

// ---------------- gating (silu(z)) + RMS norm -> fp16 ----------------
__global__ void gate_norm(const float* __restrict__ norm_w)
{
    const int row = blockIdx.x;
    const int t = threadIdx.x;
    __shared__ float red[256];
    float vals[8];
    float local = 0.f;
    const float* yrow = g_y + (size_t)row * DINNER;
    const float* zrow = g_zxbcdt + (size_t)row * DIP;
    #pragma unroll
    for (int e = 0; e < 8; e++) {
        int i = e * 256 + t;
        float zv = zrow[i];
        float gv = yrow[i] * zv / (1.f + __expf(-zv));
        vals[e] = gv;
        local += gv * gv;
    }
    red[t] = local;
    __syncthreads();
    for (int off = 128; off > 0; off >>= 1) {
        if (t < off) red[t] += red[t + off];
        __syncthreads();
    }
    float scale = rsqrtf(red[0] / (float)DINNER + 1e-5f);
    __half* out = g_yg_h + (size_t)row * DINNER;
    #pragma unroll
    for (int e = 0; e < 8; e++) {
        int i = e * 256 + t;
        out[i] = __float2half(vals[e] * scale * norm_w[i]);
    }
}

// ---------------- host launcher ----------------
extern "C" void kernel_launch(void* const* d_in, const int* in_sizes, int n_in,
                              void* d_out, int out_size)
{
    const float* u       = (const float*)d_in[0];
    const float* W_in    = (const float*)d_in[1];
    const float* conv_w  = (const float*)d_in[2];
    const float* conv_b  = (const float*)d_in[3];
    const float* dt_bias = (const float*)d_in[4];
    const float* A_log   = (const float*)d_in[5];
    const float* Dp      = (const float*)d_in[6];
    const float* norm_w  = (const float*)d_in[7];
    const float* W_out   = (const float*)d_in[8];
    float* out = (float*)d_out;

    float *zx, *cbt;
    __half *uh, *wih, *woh, *bch, *ygh;
    cudaGetSymbolAddress((void**)&zx,  g_zxbcdt);
    cudaGetSymbolAddress((void**)&cbt, g_CBT);
    cudaGetSymbolAddress((void**)&uh,  g_u_h);
    cudaGetSymbolAddress((void**)&wih, g_Win_h);
    cudaGetSymbolAddress((void**)&woh, g_Wout_h);
    cudaGetSymbolAddress((void**)&bch, g_bc_h);
    cudaGetSymbolAddress((void**)&ygh, g_yg_h);

    const int gemmSmem = GSTG * (A_STG_B + B_STG_B);  // 92160 B
    cudaFuncSetAttribute(gemm_fp16_nt,
                         cudaFuncAttributeMaxDynamicSharedMemorySize, gemmSmem);

    // 0) convert dense-GEMM inputs to fp16
    {
        int nu = BB * LL * DM;
        round_fp16<<<(nu / 4 + 255) / 256, 256>>>(u, uh, nu);
        int nwi = DIP * DM;
        round_fp16<<<(nwi / 4 + 255) / 256, 256>>>(W_in, wih, nwi);
        int nwo = DM * DINNER;
        round_fp16<<<(nwo / 4 + 255) / 256, 256>>>(W_out, woh, nwo);
    }

    // 1) in-proj (fp16 MMA)
    gemm_fp16_nt<<<dim3((DIP + 127) / 128, (BB * LL) / 256, 1), 256, gemmSmem>>>(
        uh, DM, 0, wih, DM, 0, zx, DIP, 0, DIP, DM);

    // 2) conv + silu + dt softplus
    conv_silu_dt<<<dim3(CONVD / 256, BB * LL), 256>>>(conv_w, conv_b, dt_bias);

    // 3) per-chunk cumsum of dA
    chunk_cumsum<<<BB * NH * NC, CS>>>(A_log);

    // 4) CBT[b,c] = C @ B^T (fp16 MMA)
    gemm_fp16_nt<<<dim3(2, 1, BB * NC), 256, gemmSmem>>>(
        bch + NS, 2 * NS, (long long)CS * 2 * NS,
        bch,      2 * NS, (long long)CS * 2 * NS,
        cbt, CS, (long long)CS * CS,
        CS, NS);

    // 5) per-chunk states (fp16 MMA)
    states_fp16<<<BB * NC * NH, 256>>>();

    // 6) inter-chunk scan
    chunk_scan<<<dim3(BB * NH, (HP * NS) / 256), 256>>>();

    // 7) Y = diag + off + D*x (fp16 MMA)
    y_fp16<<<dim3(2, BB * NC * NH), 256>>>(Dp);

    // 8) gating + RMS norm (fp16 output)
    gate_norm<<<BB * LL, 256>>>(norm_w);

    // 9) out-proj (fp16 MMA)
    gemm_fp16_nt<<<dim3(DM / 128, (BB * LL) / 256, 1), 256, gemmSmem>>>(
        ygh, DINNER, 0, woh, DINNER, 0, out, DM, 0, DM, DINNER);
}

// round 14
// speedup vs baseline: 1.7495x; 1.0478x over previous
#include <cuda_runtime.h>
#include <cuda_fp16.h>
#include <math.h>
#include <stdint.h>

// ---------------- problem constants ----------------
#define BB 4
#define LL 2048
#define DM 1024
#define DIP 4368          // 2*D_INNER + 2*D_STATE + NHEADS
#define DINNER 2048
#define CONVD 2304        // D_INNER + 2*D_STATE
#define NH 16
#define HP 128            // head dim
#define NS 128            // state dim
#define CS 256            // chunk size
#define NC 8              // chunks per sequence

// ---------------- scratch (device globals; no allocation) ----------------
__device__ float g_zxbcdt[(size_t)BB * LL * DIP];     // in-proj output
__device__ __half g_xc_h[(size_t)BB * LL * CONVD];    // conv+silu output (fp16)
__device__ float g_dt[(size_t)BB * LL * NH];          // softplus(dt)
__device__ float g_Acs[(size_t)BB * NH * NC * CS];    // per-chunk inclusive cumsum of dA
__device__ float g_CBT[(size_t)BB * NC * CS * CS];    // C @ B^T per (b,chunk)
__device__ __half g_states_h[(size_t)BB * NC * NH * HP * NS];
__device__ __half g_prev_h[(size_t)BB * NC * NH * HP * NS];
__device__ float g_y[(size_t)BB * LL * DINNER];       // pre-out-proj activations
__device__ __half g_u_h[(size_t)BB * LL * DM];        // fp16 u
__device__ __half g_Win_h[(size_t)DIP * DM];          // fp16 W_in
__device__ __half g_Wout_h[(size_t)DM * DINNER];      // fp16 W_out
__device__ __half g_yg_h[(size_t)BB * LL * DINNER];   // fp16 gated+normed y

// ---------------- helpers ----------------
__device__ __forceinline__ void mma_fp16(float c[4], const uint32_t a[4], const uint32_t b[2]) {
    asm volatile(
        "mma.sync.aligned.m16n8k16.row.col.f32.f16.f16.f32 "
        "{%0,%1,%2,%3}, {%4,%5,%6,%7}, {%8,%9}, {%0,%1,%2,%3};"
        : "+f"(c[0]), "+f"(c[1]), "+f"(c[2]), "+f"(c[3])
        : "r"(a[0]), "r"(a[1]), "r"(a[2]), "r"(a[3]), "r"(b[0]), "r"(b[1]));
}

__device__ __forceinline__ void ldsm4(uint32_t& r0, uint32_t& r1, uint32_t& r2, uint32_t& r3,
                                      uint32_t addr) {
    asm volatile("ldmatrix.sync.aligned.m8n8.x4.shared.b16 {%0,%1,%2,%3}, [%4];"
                 : "=r"(r0), "=r"(r1), "=r"(r2), "=r"(r3) : "r"(addr));
}

__device__ __forceinline__ void ldsm4t(uint32_t& r0, uint32_t& r1, uint32_t& r2, uint32_t& r3,
                                       uint32_t addr) {
    asm volatile("ldmatrix.sync.aligned.m8n8.x4.trans.shared.b16 {%0,%1,%2,%3}, [%4];"
                 : "=r"(r0), "=r"(r1), "=r"(r2), "=r"(r3) : "r"(addr));
}

__device__ __forceinline__ void cp16(uint32_t dst, const void* src, bool ok) {
    int sz = ok ? 16 : 0;
    asm volatile("cp.async.ca.shared.global [%0], [%1], 16, %2;\n"
                 :: "r"(dst), "l"(src), "r"(sz));
}
#define CP_COMMIT() asm volatile("cp.async.commit_group;\n")
#define CP_WAIT1()  asm volatile("cp.async.wait_group 1;\n" ::: "memory")

// ---------------- elementwise fp32 -> fp16 ----------------
__global__ void round_fp16(const float* __restrict__ s, __half* __restrict__ d, int n)
{
    int i = (blockIdx.x * 256 + threadIdx.x) * 4;
    if (i >= n) return;
    float4 v = *(const float4*)(s + i);
    *(__half2*)(d + i)     = __floats2half2_rn(v.x, v.y);
    *(__half2*)(d + i + 2) = __floats2half2_rn(v.z, v.w);
}

// ---------------- fp16 NT GEMM: 256 threads, 8 warps, 256x128 CTA tile ----------------
// (round-12 known-good, unchanged)
#define GSTG 3
#define A_STG_B (256 * 80)
#define B_STG_B (128 * 80)
#define GB_OFF (GSTG * A_STG_B)
__global__ __launch_bounds__(256, 1) void gemm_fp16_nt(
    const __half* __restrict__ A, int lda, long long sA,
    const __half* __restrict__ B, int ldb, long long sB,
    float* __restrict__ C, int ldc, long long sC,
    int N, int K)
{
    extern __shared__ char smraw[];
    const __half* Ab = A + (size_t)blockIdx.z * sA;
    const __half* Bb = B + (size_t)blockIdx.z * sB;
    float* Cb = C + (size_t)blockIdx.z * sC;
    const int m0 = blockIdx.y * 256, n0 = blockIdx.x * 128;
    const int t = threadIdx.x;
    const int lane = t & 31, w = t >> 5;
    const int wm = (w >> 1) * 64, wn = (w & 1) * 64;

    const bool bldr = (t < 128);
    const bool bok = bldr && ((n0 + t) < N);
    const __half* aS = Ab + (size_t)(m0 + t) * lda;
    const __half* bS = Bb + (size_t)(bok ? n0 + t : 0) * ldb;
    const uint32_t smBase = (uint32_t)__cvta_generic_to_shared(smraw);
    const uint32_t dA = smBase + t * 80;
    const uint32_t dB = smBase + GB_OFF + t * 80;

    const uint32_t aFragOff = (uint32_t)((wm + (lane & 15)) * 80 + (lane >> 4) * 16);
    const uint32_t bFragOff = (uint32_t)((wn + ((lane >> 4) << 3) + (lane & 7)) * 80
                                         + ((lane >> 3) & 1) * 16);

    float acc[4][8][4];
    #pragma unroll
    for (int i = 0; i < 4; i++)
        #pragma unroll
        for (int j = 0; j < 8; j++)
            #pragma unroll
            for (int q = 0; q < 4; q++) acc[i][j][q] = 0.f;

    const int nIter = K >> 5;
    #pragma unroll
    for (int s = 0; s < GSTG - 1; s++) {
        const uint32_t offA = s * A_STG_B;
        const uint32_t offB = s * B_STG_B;
        const int k0 = s << 5;
        cp16(dA + offA,      aS + k0,      true);
        cp16(dA + offA + 16, aS + k0 + 8,  true);
        cp16(dA + offA + 32, aS + k0 + 16, true);
        cp16(dA + offA + 48, aS + k0 + 24, true);
        if (bldr) {
            cp16(dB + offB,      bS + k0,      bok);
            cp16(dB + offB + 16, bS + k0 + 8,  bok);
            cp16(dB + offB + 32, bS + k0 + 16, bok);
            cp16(dB + offB + 48, bS + k0 + 24, bok);
        }
        CP_COMMIT();
    }

    for (int it = 0; it < nIter; it++) {
        CP_WAIT1();
        __syncthreads();
        const int pf = it + GSTG - 1;
        if (pf < nIter) {
            const uint32_t offA = (pf % GSTG) * A_STG_B;
            const uint32_t offB = (pf % GSTG) * B_STG_B;
            const int k0 = pf << 5;
            cp16(dA + offA,      aS + k0,      true);
            cp16(dA + offA + 16, aS + k0 + 8,  true);
            cp16(dA + offA + 32, aS + k0 + 16, true);
            cp16(dA + offA + 48, aS + k0 + 24, true);
            if (bldr) {
                cp16(dB + offB,      bS + k0,      bok);
                cp16(dB + offB + 16, bS + k0 + 8,  bok);
                cp16(dB + offB + 32, bS + k0 + 16, bok);
                cp16(dB + offB + 48, bS + k0 + 24, bok);
            }
        }
        CP_COMMIT();

        const uint32_t aOct = smBase + (it % GSTG) * A_STG_B + aFragOff;
        const uint32_t bOct = smBase + GB_OFF + (it % GSTG) * B_STG_B + bFragOff;
        #pragma unroll
        for (int kk = 0; kk < 64; kk += 32) {
            uint32_t afr[4][4], bfr[8][2];
            #pragma unroll
            for (int mi = 0; mi < 4; mi++)
                ldsm4(afr[mi][0], afr[mi][1], afr[mi][2], afr[mi][3],
                      aOct + kk + mi * (16 * 80));
            #pragma unroll
            for (int j = 0; j < 4; j++)
                ldsm4(bfr[2 * j][0], bfr[2 * j][1], bfr[2 * j + 1][0], bfr[2 * j + 1][1],
                      bOct + kk + j * (16 * 80));
            #pragma unroll
            for (int mi = 0; mi < 4; mi++)
                #pragma unroll
                for (int ni = 0; ni < 8; ni++)
                    mma_fp16(acc[mi][ni], afr[mi], bfr[ni]);
        }
    }

    const int g = lane >> 2, tt = lane & 3;
    #pragma unroll
    for (int mi = 0; mi < 4; mi++) {
        #pragma unroll
        for (int ni = 0; ni < 8; ni++) {
            int row = m0 + wm + mi * 16 + g;
            int col = n0 + wn + ni * 8 + 2 * tt;
            if (col < N) {
                *(float2*)(Cb + (size_t)row * ldc + col) =
                    make_float2(acc[mi][ni][0], acc[mi][ni][1]);
                *(float2*)(Cb + (size_t)(row + 8) * ldc + col) =
                    make_float2(acc[mi][ni][2], acc[mi][ni][3]);
            }
        }
    }
}

// ---------------- depthwise conv (K=4) + SiLU + dt softplus (fp16 output) ----------------
__global__ void conv_silu_dt(const float* __restrict__ conv_w,
                             const float* __restrict__ conv_b,
                             const float* __restrict__ dt_bias)
{
    const int bl = blockIdx.y;
    const int l = bl & (LL - 1);
    const int c = blockIdx.x * 256 + threadIdx.x;
    float acc = conv_b[c];
    #pragma unroll
    for (int k = 0; k < 4; k++) {
        int ls = l + k - 3;
        if (ls >= 0)
            acc += g_zxbcdt[(size_t)(bl + k - 3) * DIP + DINNER + c] * conv_w[c * 4 + k];
    }
    acc = acc / (1.f + __expf(-acc));
    g_xc_h[(size_t)bl * CONVD + c] = __float2half(acc);

    if (blockIdx.x == 0 && threadIdx.x < NH) {
        float x = g_zxbcdt[(size_t)bl * DIP + DINNER + CONVD + threadIdx.x] + dt_bias[threadIdx.x];
        float sp = (x > 20.f) ? x : log1pf(__expf(x));
        g_dt[(size_t)bl * NH + threadIdx.x] = sp;
    }
}

// ---------------- per-chunk inclusive cumsum of dA = dt * A ----------------
__global__ void chunk_cumsum(const float* __restrict__ A_log)
{
    const int idx = blockIdx.x;
    const int c = idx % NC;
    const int h = (idx / NC) % NH;
    const int b = idx / (NC * NH);
    const int s = threadIdx.x;
    __shared__ float sh[CS];
    float Ah = -__expf(A_log[h]);
    sh[s] = g_dt[((size_t)b * LL + c * CS + s) * NH + h] * Ah;
    __syncthreads();
    for (int off = 1; off < CS; off <<= 1) {
        float u = (s >= off) ? sh[s - off] : 0.f;
        __syncthreads();
        sh[s] += u;
        __syncthreads();
    }
    g_Acs[(size_t)idx * CS + s] = sh[s];
}

// ---------------- states (fp16 MMA, 256 threads, trans ldmatrix) ----------------
#define KM_STRIDE 272   // bytes per k-row (128 halves + 8 pad)
__global__ __launch_bounds__(256, 2) void states_fp16()
{
    const int z = blockIdx.x;
    const int h = z % NH;
    const int bc = z / NH;
    const int c = bc % NC;
    const int b = bc / NC;
    __shared__ __half Xs[16][136];
    __shared__ __half Bs[16][136];
    __shared__ float ws[CS];
    const int t = threadIdx.x;
    {
        const float* acs = g_Acs + ((size_t)(b * NH + h) * NC + c) * CS;
        float last = acs[CS - 1];
        float dtv = g_dt[((size_t)b * LL + c * CS + t) * NH + h];
        ws[t] = dtv * __expf(last - acs[t]);
    }
    __syncthreads();
    const int lane = t & 31, w = t >> 5;
    const int wm = (w & 1) * 64, wn = (w >> 1) * 32;
    const int lr = t >> 4, lc = (t & 15) * 8;
    const uint32_t smX = (uint32_t)__cvta_generic_to_shared(&Xs[0][0]);
    const uint32_t smB = (uint32_t)__cvta_generic_to_shared(&Bs[0][0]);
    const uint32_t aRowOff = (uint32_t)(((lane & 7) + ((lane >> 4) << 3)) * KM_STRIDE
                                        + ((lane >> 3) & 1) * 16);
    const uint32_t bRowOff = (uint32_t)(((lane & 7) + ((lane >> 3) & 1) * 8) * KM_STRIDE
                                        + ((lane >> 4) << 4));

    float acc[4][4][4];
    #pragma unroll
    for (int i = 0; i < 4; i++)
        #pragma unroll
        for (int j = 0; j < 4; j++)
            #pragma unroll
            for (int q = 0; q < 4; q++) acc[i][j][q] = 0.f;

    const __half* xbase = g_xc_h + ((size_t)b * LL + c * CS) * CONVD + h * HP;
    const __half* bbase = g_xc_h + ((size_t)b * LL + c * CS) * CONVD + DINNER;

    for (int k0 = 0; k0 < CS; k0 += 16) {
        const __half2 wsv2 = __float2half2_rn(ws[k0 + lr]);
        const __half* xr = xbase + (size_t)(k0 + lr) * CONVD + lc;
        const __half* br = bbase + (size_t)(k0 + lr) * CONVD + lc;
        uint4 xv = *(const uint4*)(xr);
        __half2* xp = (__half2*)&xv;
        #pragma unroll
        for (int q = 0; q < 4; q++) xp[q] = __hmul2(xp[q], wsv2);
        *(uint4*)&Xs[lr][lc] = xv;
        *(uint4*)&Bs[lr][lc] = *(const uint4*)(br);
        __syncthreads();
        uint32_t afr[4][4], bfr[4][2];
        #pragma unroll
        for (int mi = 0; mi < 4; mi++)
            ldsm4t(afr[mi][0], afr[mi][1], afr[mi][2], afr[mi][3],
                   smX + aRowOff + (wm + mi * 16) * 2);
        #pragma unroll
        for (int np = 0; np < 2; np++)
            ldsm4t(bfr[2 * np][0], bfr[2 * np][1], bfr[2 * np + 1][0], bfr[2 * np + 1][1],
                   smB + bRowOff + (wn + np * 16) * 2);
        #pragma unroll
        for (int mi = 0; mi < 4; mi++)
            #pragma unroll
            for (int ni = 0; ni < 4; ni++)
                mma_fp16(acc[mi][ni], afr[mi], bfr[ni]);
        __syncthreads();
    }

    __half* sout = g_states_h + (size_t)z * HP * NS;
    const int g = lane >> 2, tt = lane & 3;
    #pragma unroll
    for (int mi = 0; mi < 4; mi++)
        #pragma unroll
        for (int ni = 0; ni < 4; ni++) {
            int row = wm + mi * 16 + g;
            int col = wn + ni * 8 + 2 * tt;
            *(__half2*)(sout + (size_t)row * NS + col) =
                __floats2half2_rn(acc[mi][ni][0], acc[mi][ni][1]);
            *(__half2*)(sout + (size_t)(row + 8) * NS + col) =
                __floats2half2_rn(acc[mi][ni][2], acc[mi][ni][3]);
        }
}

// ---------------- sequential scan over chunks (half2, element-parallel) ----------------
__global__ void chunk_scan()
{
    const int bh = blockIdx.x;
    const int b = bh / NH, h = bh % NH;
    __shared__ float dec[NC];
    if (threadIdx.x < NC)
        dec[threadIdx.x] = __expf(g_Acs[((size_t)(b * NH + h) * NC + threadIdx.x) * CS + CS - 1]);
    __syncthreads();
    const int idx = (blockIdx.y * 256 + threadIdx.x) * 2;
    float2 carry = make_float2(0.f, 0.f);
    #pragma unroll
    for (int c = 0; c < NC; c++) {
        size_t base = ((size_t)((b * NC + c) * NH + h)) * HP * NS + idx;
        *(__half2*)(g_prev_h + base) = __floats2half2_rn(carry.x, carry.y);
        float2 s = __half22float2(*(const __half2*)(g_states_h + base));
        carry.x = carry.x * dec[c] + s.x;
        carry.y = carry.y * dec[c] + s.y;
    }
}

// ---------------- Y (fp16 MMA, 256 threads) ----------------
#define RM_STRIDE 48    // bytes per row (16 halves + 8 pad)
__global__ __launch_bounds__(256, 2) void y_fp16(const float* __restrict__ Dp)
{
    const int z = blockIdx.y;
    const int h = z % NH;
    const int bc = z / NH;
    const int c = bc % NC;
    const int b = bc / NC;
    const int m0 = blockIdx.x * 128;

    __shared__ float sAcs[CS], sdt[CS];
    __shared__ float sh_e[16];
    __shared__ __half As[128][24];
    __shared__ __half Bt[16][136];
    __shared__ __half B2[128][24];
    const int t = threadIdx.x;
    {
        const float* acs = g_Acs + ((size_t)(b * NH + h) * NC + c) * CS;
        sAcs[t] = acs[t];
        sdt[t] = g_dt[((size_t)b * LL + c * CS + t) * NH + h];
    }
    __syncthreads();

    const int lane = t & 31, w = t >> 5;
    const int wm = (w & 1) * 64, wn = (w >> 1) * 32;
    const int arow = t >> 1, ac8 = (t & 1) * 8;
    const int l_loc = m0 + arow;
    const float acs_l = sAcs[l_loc];
    const __half2 eAl2 = __float2half2_rn(__expf(acs_l));
    const int xr16 = t >> 4, xc8 = (t & 15) * 8;

    const uint32_t smA  = (uint32_t)__cvta_generic_to_shared(&As[0][0]);
    const uint32_t smBt = (uint32_t)__cvta_generic_to_shared(&Bt[0][0]);
    const uint32_t smB2 = (uint32_t)__cvta_generic_to_shared(&B2[0][0]);
    const uint32_t aFrag  = (uint32_t)((wm + (lane & 15)) * RM_STRIDE + (lane >> 4) * 16);
    const uint32_t btFrag = (uint32_t)(((lane & 7) + ((lane >> 3) & 1) * 8) * KM_STRIDE
                                       + ((lane >> 4) << 4));
    const uint32_t b2Frag = (uint32_t)((wn + ((lane >> 4) << 3) + (lane & 7)) * RM_STRIDE
                                       + ((lane >> 3) & 1) * 16);

    float acc[4][4][4];
    #pragma unroll
    for (int i = 0; i < 4; i++)
        #pragma unroll
        for (int j = 0; j < 4; j++)
            #pragma unroll
            for (int q = 0; q < 4; q++) acc[i][j][q] = 0.f;

    const float* cbt_l = g_CBT + (size_t)bc * CS * CS + (size_t)l_loc * CS;
    const __half* xrow = g_xc_h + ((size_t)b * LL + c * CS) * CONVD + h * HP;

    // ---- phase 1: intra-chunk, K = m0+128 (factorized decay exp) ----
    const int K1 = m0 + 128;
    for (int k0 = 0; k0 < K1; k0 += 16) {
        if (t < 16)
            sh_e[t] = __expf(sAcs[k0 + 15] - sAcs[k0 + t]) * sdt[k0 + t];
        __syncthreads();
        const float e_row = (l_loc >= k0) ? __expf(acs_l - sAcs[k0 + 15]) : 0.f;
        #pragma unroll
        for (int j = 0; j < 8; j += 2) {
            int s = k0 + ac8 + j;
            float v0 = (s     <= l_loc) ? cbt_l[s]     * e_row * sh_e[ac8 + j]     : 0.f;
            float v1 = (s + 1 <= l_loc) ? cbt_l[s + 1] * e_row * sh_e[ac8 + j + 1] : 0.f;
            *(__half2*)&As[arow][ac8 + j] = __floats2half2_rn(v0, v1);
        }
        const __half* xr = xrow + (size_t)(k0 + xr16) * CONVD + xc8;
        *(uint4*)&Bt[xr16][xc8] = *(const uint4*)(xr);
        __syncthreads();
        uint32_t afr[4][4], bfr[4][2];
        #pragma unroll
        for (int mi = 0; mi < 4; mi++)
            ldsm4(afr[mi][0], afr[mi][1], afr[mi][2], afr[mi][3],
                  smA + aFrag + mi * (16 * RM_STRIDE));
        #pragma unroll
        for (int np = 0; np < 2; np++)
            ldsm4t(bfr[2 * np][0], bfr[2 * np][1], bfr[2 * np + 1][0], bfr[2 * np + 1][1],
                   smBt + btFrag + (wn + np * 16) * 2);
        #pragma unroll
        for (int mi = 0; mi < 4; mi++)
            #pragma unroll
            for (int ni = 0; ni < 4; ni++)
                mma_fp16(acc[mi][ni], afr[mi], bfr[ni]);
        __syncthreads();
    }

    // ---- phase 2: inter-chunk, K = NS = 128 ----
    const __half* crow = g_xc_h + ((size_t)b * LL + c * CS) * CONVD + DINNER + NS;
    const __half* prow = g_prev_h + (size_t)z * HP * NS;
    for (int k0 = 0; k0 < NS; k0 += 16) {
        const __half* cr = crow + (size_t)l_loc * CONVD + k0 + ac8;
        uint4 cv = *(const uint4*)(cr);
        __half2* cp = (__half2*)&cv;
        #pragma unroll
        for (int q = 0; q < 4; q++) cp[q] = __hmul2(cp[q], eAl2);
        *(uint4*)&As[arow][ac8] = cv;
        const __half* pr = prow + (size_t)arow * NS + k0 + ac8;
        *(uint4*)&B2[arow][ac8] = *(const uint4*)(pr);
        __syncthreads();
        uint32_t afr[4][4], bfr[4][2];
        #pragma unroll
        for (int mi = 0; mi < 4; mi++)
            ldsm4(afr[mi][0], afr[mi][1], afr[mi][2], afr[mi][3],
                  smA + aFrag + mi * (16 * RM_STRIDE));
        #pragma unroll
        for (int np = 0; np < 2; np++)
            ldsm4(bfr[2 * np][0], bfr[2 * np][1], bfr[2 * np + 1][0], bfr[2 * np + 1][1],
                  smB2 + b2Frag + np * (16 * RM_STRIDE));
        #pragma unroll
        for (int mi = 0; mi < 4; mi++)
            #pragma unroll
            for (int ni = 0; ni < 4; ni++)
                mma_fp16(acc[mi][ni], afr[mi], bfr[ni]);
        __syncthreads();
    }

    const float Dh = Dp[h];
    const int g = lane >> 2, tt = lane & 3;
    #pragma unroll
    for (int mi = 0; mi < 4; mi++)
        #pragma unroll
        for (int ni = 0; ni < 4; ni++) {
            int l0 = m0 + wm + mi * 16 + g;
            int p = wn + ni * 8 + 2 * tt;
            float2 xv0 = __half22float2(*(const __half2*)(xrow + (size_t)l0 * CONVD + p));
            float2 xv1 = __half22float2(*(const __half2*)(xrow + (size_t)(l0 + 8) * CONVD + p));
            float* o0 = g_y + ((size_t)b * LL + c * CS + l0) * DINNER + h * HP + p;
            float* o1 = g_y + ((size_t)b * LL + c * CS + l0 + 8) * DINNER + h * HP + p;
            *(float2*)o0 = make_float2(acc[mi][ni][0] + Dh * xv0.x,
                                       acc[mi][ni][1] + Dh * xv0.y);
            *(float2*)o1 = make_float2(acc[mi][ni][2] + Dh * xv1.x,
                                       acc[mi][ni][3] + Dh * xv1.y);
        }
}

// ---------------- gating (silu(z)) + RMS norm -> fp16 ----------------
__global__ void gate_norm(const float* __restrict__ norm_w)
{
    const int row = blockIdx.x;
    const int t = threadIdx.x;
    __shared__ float red[256];
    float vals[8];
    float local = 0.f;
    const float* yrow = g_y + (size_t)row * DINNER;
    const float* zrow = g_zxbcdt + (size_t)row * DIP;
    #pragma unroll
    for (int e = 0; e < 8; e++) {
        int i = e * 256 + t;
        float zv = zrow[i];
        float gv = yrow[i] * zv / (1.f + __expf(-zv));
        vals[e] = gv;
        local += gv * gv;
    }
    red[t] = local;
    __syncthreads();
    for (int off = 128; off > 0; off >>= 1) {
        if (t < off) red[t] += red[t + off];
        __syncthreads();
    }
    float scale = rsqrtf(red[0] / (float)DINNER + 1e-5f);
    __half* out = g_yg_h + (size_t)row * DINNER;
    #pragma unroll
    for (int e = 0; e < 8; e++) {
        int i = e * 256 + t;
        out[i] = __float2half(vals[e] * scale * norm_w[i]);
    }
}

// ---------------- host launcher ----------------
extern "C" void kernel_launch(void* const* d_in, const int* in_sizes, int n_in,
                              void* d_out, int out_size)
{
    const float* u       = (const float*)d_in[0];
    const float* W_in    = (const float*)d_in[1];
    const float* conv_w  = (const float*)d_in[2];
    const float* conv_b  = (const float*)d_in[3];
    const float* dt_bias = (const float*)d_in[4];
    const float* A_log   = (const float*)d_in[5];
    const float* Dp      = (const float*)d_in[6];
    const float* norm_w  = (const float*)d_in[7];
    const float* W_out   = (const float*)d_in[8];
    float* out = (float*)d_out;

    float *zx, *cbt;
    __half *uh, *wih, *woh, *xch, *ygh;
    cudaGetSymbolAddress((void**)&zx,  g_zxbcdt);
    cudaGetSymbolAddress((void**)&cbt, g_CBT);
    cudaGetSymbolAddress((void**)&uh,  g_u_h);
    cudaGetSymbolAddress((void**)&wih, g_Win_h);
    cudaGetSymbolAddress((void**)&woh, g_Wout_h);
    cudaGetSymbolAddress((void**)&xch, g_xc_h);
    cudaGetSymbolAddress((void**)&ygh, g_yg_h);

    const int gemmSmem = GSTG * (A_STG_B + B_STG_B);  // 92160 B
    cudaFuncSetAttribute(gemm_fp16_nt,
                         cudaFuncAttributeMaxDynamicSharedMemorySize, gemmSmem);

    // 0) convert dense-GEMM inputs to fp16
    {
        int nu = BB * LL * DM;
        round_fp16<<<(nu / 4 + 255) / 256, 256>>>(u, uh, nu);
        int nwi = DIP * DM;
        round_fp16<<<(nwi / 4 + 255) / 256, 256>>>(W_in, wih, nwi);
        int nwo = DM * DINNER;
        round_fp16<<<(nwo / 4 + 255) / 256, 256>>>(W_out, woh, nwo);
    }

    // 1) in-proj (fp16 MMA)
    gemm_fp16_nt<<<dim3((DIP + 127) / 128, (BB * LL) / 256, 1), 256, gemmSmem>>>(
        uh, DM, 0, wih, DM, 0, zx, DIP, 0, DIP, DM);

    // 2) conv + silu + dt softplus (fp16 xc)
    conv_silu_dt<<<dim3(CONVD / 256, BB * LL), 256>>>(conv_w, conv_b, dt_bias);

    // 3) per-chunk cumsum of dA
    chunk_cumsum<<<BB * NH * NC, CS>>>(A_log);

    // 4) CBT[b,c] = C @ B^T (fp16 MMA, B/C straight out of g_xc_h)
    gemm_fp16_nt<<<dim3(2, 1, BB * NC), 256, gemmSmem>>>(
        xch + DINNER + NS, CONVD, (long long)CS * CONVD,
        xch + DINNER,      CONVD, (long long)CS * CONVD,
        cbt, CS, (long long)CS * CS,
        CS, NS);

    // 5) per-chunk states (fp16 MMA)
    states_fp16<<<BB * NC * NH, 256>>>();

    // 6) inter-chunk scan (half2)
    chunk_scan<<<dim3(BB * NH, (HP * NS) / 512), 256>>>();

    // 7) Y = diag + off + D*x (fp16 MMA)
    y_fp16<<<dim3(2, BB * NC * NH), 256>>>(Dp);

    // 8) gating + RMS norm (fp16 output)
    gate_norm<<<BB * LL, 256>>>(norm_w);

    // 9) out-proj (fp16 MMA)
    gemm_fp16_nt<<<dim3(DM / 128, (BB * LL) / 256, 1), 256, gemmSmem>>>(
        ygh, DINNER, 0, woh, DINNER, 0, out, DM, 0, DM, DINNER);
}

// round 15
// speedup vs baseline: 1.7959x; 1.0265x over previous
#include <cuda_runtime.h>
#include <cuda_fp16.h>
#include <math.h>
#include <stdint.h>

// ---------------- problem constants ----------------
#define BB 4
#define LL 2048
#define DM 1024
#define DIP 4368          // 2*D_INNER + 2*D_STATE + NHEADS
#define DINNER 2048
#define CONVD 2304        // D_INNER + 2*D_STATE
#define NH 16
#define HP 128            // head dim
#define NS 128            // state dim
#define CS 256            // chunk size
#define NC 8              // chunks per sequence

// ---------------- scratch (device globals; no allocation) ----------------
__device__ __half g_zx_h[(size_t)BB * LL * DIP];      // in-proj output (fp16)
__device__ __half g_xc_h[(size_t)BB * LL * CONVD];    // conv+silu output (fp16)
__device__ float g_dt[(size_t)BB * LL * NH];          // softplus(dt)
__device__ float g_Acs[(size_t)BB * NH * NC * CS];    // per-chunk inclusive cumsum of dA
__device__ float g_CBT[(size_t)BB * NC * CS * CS];    // C @ B^T per (b,chunk)
__device__ __half g_states_h[(size_t)BB * NC * NH * HP * NS];
__device__ __half g_prev_h[(size_t)BB * NC * NH * HP * NS];
__device__ __half g_y_h[(size_t)BB * LL * DINNER];    // pre-out-proj activations (fp16)
__device__ __half g_u_h[(size_t)BB * LL * DM];        // fp16 u
__device__ __half g_Win_h[(size_t)DIP * DM];          // fp16 W_in
__device__ __half g_Wout_h[(size_t)DM * DINNER];      // fp16 W_out
__device__ __half g_yg_h[(size_t)BB * LL * DINNER];   // fp16 gated+normed y

// ---------------- helpers ----------------
__device__ __forceinline__ void mma_fp16(float c[4], const uint32_t a[4], const uint32_t b[2]) {
    asm volatile(
        "mma.sync.aligned.m16n8k16.row.col.f32.f16.f16.f32 "
        "{%0,%1,%2,%3}, {%4,%5,%6,%7}, {%8,%9}, {%0,%1,%2,%3};"
        : "+f"(c[0]), "+f"(c[1]), "+f"(c[2]), "+f"(c[3])
        : "r"(a[0]), "r"(a[1]), "r"(a[2]), "r"(a[3]), "r"(b[0]), "r"(b[1]));
}

__device__ __forceinline__ void ldsm4(uint32_t& r0, uint32_t& r1, uint32_t& r2, uint32_t& r3,
                                      uint32_t addr) {
    asm volatile("ldmatrix.sync.aligned.m8n8.x4.shared.b16 {%0,%1,%2,%3}, [%4];"
                 : "=r"(r0), "=r"(r1), "=r"(r2), "=r"(r3) : "r"(addr));
}

__device__ __forceinline__ void ldsm4t(uint32_t& r0, uint32_t& r1, uint32_t& r2, uint32_t& r3,
                                       uint32_t addr) {
    asm volatile("ldmatrix.sync.aligned.m8n8.x4.trans.shared.b16 {%0,%1,%2,%3}, [%4];"
                 : "=r"(r0), "=r"(r1), "=r"(r2), "=r"(r3) : "r"(addr));
}

__device__ __forceinline__ void cp16(uint32_t dst, const void* src, bool ok) {
    int sz = ok ? 16 : 0;
    asm volatile("cp.async.ca.shared.global [%0], [%1], 16, %2;\n"
                 :: "r"(dst), "l"(src), "r"(sz));
}
#define CP_COMMIT() asm volatile("cp.async.commit_group;\n")
#define CP_WAIT1()  asm volatile("cp.async.wait_group 1;\n" ::: "memory")

// ---------------- elementwise fp32 -> fp16 ----------------
__global__ void round_fp16(const float* __restrict__ s, __half* __restrict__ d, int n)
{
    int i = (blockIdx.x * 256 + threadIdx.x) * 4;
    if (i >= n) return;
    float4 v = *(const float4*)(s + i);
    *(__half2*)(d + i)     = __floats2half2_rn(v.x, v.y);
    *(__half2*)(d + i + 2) = __floats2half2_rn(v.z, v.w);
}

// ---------------- fp16 NT GEMM: 256 threads, 8 warps, 256x128 CTA tile ----------------
// outHalf != 0: C is __half* (writes half2); else float*.
#define GSTG 3
#define A_STG_B (256 * 80)
#define B_STG_B (128 * 80)
#define GB_OFF (GSTG * A_STG_B)
__global__ __launch_bounds__(256, 1) void gemm_fp16_nt(
    const __half* __restrict__ A, int lda, long long sA,
    const __half* __restrict__ B, int ldb, long long sB,
    void* __restrict__ C, int ldc, long long sC,
    int N, int K, int outHalf)
{
    extern __shared__ char smraw[];
    const __half* Ab = A + (size_t)blockIdx.z * sA;
    const __half* Bb = B + (size_t)blockIdx.z * sB;
    const int m0 = blockIdx.y * 256, n0 = blockIdx.x * 128;
    const int t = threadIdx.x;
    const int lane = t & 31, w = t >> 5;
    const int wm = (w >> 1) * 64, wn = (w & 1) * 64;

    const bool bldr = (t < 128);
    const bool bok = bldr && ((n0 + t) < N);
    const __half* aS = Ab + (size_t)(m0 + t) * lda;
    const __half* bS = Bb + (size_t)(bok ? n0 + t : 0) * ldb;
    const uint32_t smBase = (uint32_t)__cvta_generic_to_shared(smraw);
    const uint32_t dA = smBase + t * 80;
    const uint32_t dB = smBase + GB_OFF + t * 80;

    const uint32_t aFragOff = (uint32_t)((wm + (lane & 15)) * 80 + (lane >> 4) * 16);
    const uint32_t bFragOff = (uint32_t)((wn + ((lane >> 4) << 3) + (lane & 7)) * 80
                                         + ((lane >> 3) & 1) * 16);

    float acc[4][8][4];
    #pragma unroll
    for (int i = 0; i < 4; i++)
        #pragma unroll
        for (int j = 0; j < 8; j++)
            #pragma unroll
            for (int q = 0; q < 4; q++) acc[i][j][q] = 0.f;

    const int nIter = K >> 5;
    #pragma unroll
    for (int s = 0; s < GSTG - 1; s++) {
        const uint32_t offA = s * A_STG_B;
        const uint32_t offB = s * B_STG_B;
        const int k0 = s << 5;
        cp16(dA + offA,      aS + k0,      true);
        cp16(dA + offA + 16, aS + k0 + 8,  true);
        cp16(dA + offA + 32, aS + k0 + 16, true);
        cp16(dA + offA + 48, aS + k0 + 24, true);
        if (bldr) {
            cp16(dB + offB,      bS + k0,      bok);
            cp16(dB + offB + 16, bS + k0 + 8,  bok);
            cp16(dB + offB + 32, bS + k0 + 16, bok);
            cp16(dB + offB + 48, bS + k0 + 24, bok);
        }
        CP_COMMIT();
    }

    for (int it = 0; it < nIter; it++) {
        CP_WAIT1();
        __syncthreads();
        const int pf = it + GSTG - 1;
        if (pf < nIter) {
            const uint32_t offA = (pf % GSTG) * A_STG_B;
            const uint32_t offB = (pf % GSTG) * B_STG_B;
            const int k0 = pf << 5;
            cp16(dA + offA,      aS + k0,      true);
            cp16(dA + offA + 16, aS + k0 + 8,  true);
            cp16(dA + offA + 32, aS + k0 + 16, true);
            cp16(dA + offA + 48, aS + k0 + 24, true);
            if (bldr) {
                cp16(dB + offB,      bS + k0,      bok);
                cp16(dB + offB + 16, bS + k0 + 8,  bok);
                cp16(dB + offB + 32, bS + k0 + 16, bok);
                cp16(dB + offB + 48, bS + k0 + 24, bok);
            }
        }
        CP_COMMIT();

        const uint32_t aOct = smBase + (it % GSTG) * A_STG_B + aFragOff;
        const uint32_t bOct = smBase + GB_OFF + (it % GSTG) * B_STG_B + bFragOff;
        #pragma unroll
        for (int kk = 0; kk < 64; kk += 32) {
            uint32_t afr[4][4], bfr[8][2];
            #pragma unroll
            for (int mi = 0; mi < 4; mi++)
                ldsm4(afr[mi][0], afr[mi][1], afr[mi][2], afr[mi][3],
                      aOct + kk + mi * (16 * 80));
            #pragma unroll
            for (int j = 0; j < 4; j++)
                ldsm4(bfr[2 * j][0], bfr[2 * j][1], bfr[2 * j + 1][0], bfr[2 * j + 1][1],
                      bOct + kk + j * (16 * 80));
            #pragma unroll
            for (int mi = 0; mi < 4; mi++)
                #pragma unroll
                for (int ni = 0; ni < 8; ni++)
                    mma_fp16(acc[mi][ni], afr[mi], bfr[ni]);
        }
    }

    const int g = lane >> 2, tt = lane & 3;
    if (outHalf) {
        __half* Cb = (__half*)C + (size_t)blockIdx.z * sC;
        #pragma unroll
        for (int mi = 0; mi < 4; mi++)
            #pragma unroll
            for (int ni = 0; ni < 8; ni++) {
                int row = m0 + wm + mi * 16 + g;
                int col = n0 + wn + ni * 8 + 2 * tt;
                if (col < N) {
                    *(__half2*)(Cb + (size_t)row * ldc + col) =
                        __floats2half2_rn(acc[mi][ni][0], acc[mi][ni][1]);
                    *(__half2*)(Cb + (size_t)(row + 8) * ldc + col) =
                        __floats2half2_rn(acc[mi][ni][2], acc[mi][ni][3]);
                }
            }
    } else {
        float* Cb = (float*)C + (size_t)blockIdx.z * sC;
        #pragma unroll
        for (int mi = 0; mi < 4; mi++)
            #pragma unroll
            for (int ni = 0; ni < 8; ni++) {
                int row = m0 + wm + mi * 16 + g;
                int col = n0 + wn + ni * 8 + 2 * tt;
                if (col < N) {
                    *(float2*)(Cb + (size_t)row * ldc + col) =
                        make_float2(acc[mi][ni][0], acc[mi][ni][1]);
                    *(float2*)(Cb + (size_t)(row + 8) * ldc + col) =
                        make_float2(acc[mi][ni][2], acc[mi][ni][3]);
                }
            }
    }
}

// ---------------- depthwise conv (K=4) + SiLU + dt softplus ----------------
__global__ void conv_silu_dt(const float* __restrict__ conv_w,
                             const float* __restrict__ conv_b,
                             const float* __restrict__ dt_bias)
{
    const int bl = blockIdx.y;
    const int l = bl & (LL - 1);
    const int c = blockIdx.x * 256 + threadIdx.x;
    float acc = conv_b[c];
    #pragma unroll
    for (int k = 0; k < 4; k++) {
        int ls = l + k - 3;
        if (ls >= 0)
            acc += __half2float(g_zx_h[(size_t)(bl + k - 3) * DIP + DINNER + c])
                   * conv_w[c * 4 + k];
    }
    acc = acc / (1.f + __expf(-acc));
    g_xc_h[(size_t)bl * CONVD + c] = __float2half(acc);

    if (blockIdx.x == 0 && threadIdx.x < NH) {
        float x = __half2float(g_zx_h[(size_t)bl * DIP + DINNER + CONVD + threadIdx.x])
                  + dt_bias[threadIdx.x];
        float sp = (x > 20.f) ? x : log1pf(__expf(x));
        g_dt[(size_t)bl * NH + threadIdx.x] = sp;
    }
}

// ---------------- per-chunk inclusive cumsum of dA = dt * A ----------------
__global__ void chunk_cumsum(const float* __restrict__ A_log)
{
    const int idx = blockIdx.x;
    const int c = idx % NC;
    const int h = (idx / NC) % NH;
    const int b = idx / (NC * NH);
    const int s = threadIdx.x;
    __shared__ float sh[CS];
    float Ah = -__expf(A_log[h]);
    sh[s] = g_dt[((size_t)b * LL + c * CS + s) * NH + h] * Ah;
    __syncthreads();
    for (int off = 1; off < CS; off <<= 1) {
        float u = (s >= off) ? sh[s - off] : 0.f;
        __syncthreads();
        sh[s] += u;
        __syncthreads();
    }
    g_Acs[(size_t)idx * CS + s] = sh[s];
}

// ---------------- states (fp16 MMA, 256 threads, trans ldmatrix) ----------------
#define KM_STRIDE 272   // bytes per k-row (128 halves + 8 pad)
__global__ __launch_bounds__(256, 2) void states_fp16()
{
    const int z = blockIdx.x;
    const int h = z % NH;
    const int bc = z / NH;
    const int c = bc % NC;
    const int b = bc / NC;
    __shared__ __half Xs[16][136];
    __shared__ __half Bs[16][136];
    __shared__ float ws[CS];
    const int t = threadIdx.x;
    {
        const float* acs = g_Acs + ((size_t)(b * NH + h) * NC + c) * CS;
        float last = acs[CS - 1];
        float dtv = g_dt[((size_t)b * LL + c * CS + t) * NH + h];
        ws[t] = dtv * __expf(last - acs[t]);
    }
    __syncthreads();
    const int lane = t & 31, w = t >> 5;
    const int wm = (w & 1) * 64, wn = (w >> 1) * 32;
    const int lr = t >> 4, lc = (t & 15) * 8;
    const uint32_t smX = (uint32_t)__cvta_generic_to_shared(&Xs[0][0]);
    const uint32_t smB = (uint32_t)__cvta_generic_to_shared(&Bs[0][0]);
    const uint32_t aRowOff = (uint32_t)(((lane & 7) + ((lane >> 4) << 3)) * KM_STRIDE
                                        + ((lane >> 3) & 1) * 16);
    const uint32_t bRowOff = (uint32_t)(((lane & 7) + ((lane >> 3) & 1) * 8) * KM_STRIDE
                                        + ((lane >> 4) << 4));

    float acc[4][4][4];
    #pragma unroll
    for (int i = 0; i < 4; i++)
        #pragma unroll
        for (int j = 0; j < 4; j++)
            #pragma unroll
            for (int q = 0; q < 4; q++) acc[i][j][q] = 0.f;

    const __half* xbase = g_xc_h + ((size_t)b * LL + c * CS) * CONVD + h * HP;
    const __half* bbase = g_xc_h + ((size_t)b * LL + c * CS) * CONVD + DINNER;

    for (int k0 = 0; k0 < CS; k0 += 16) {
        const __half2 wsv2 = __float2half2_rn(ws[k0 + lr]);
        const __half* xr = xbase + (size_t)(k0 + lr) * CONVD + lc;
        const __half* br = bbase + (size_t)(k0 + lr) * CONVD + lc;
        uint4 xv = *(const uint4*)(xr);
        __half2* xp = (__half2*)&xv;
        #pragma unroll
        for (int q = 0; q < 4; q++) xp[q] = __hmul2(xp[q], wsv2);
        *(uint4*)&Xs[lr][lc] = xv;
        *(uint4*)&Bs[lr][lc] = *(const uint4*)(br);
        __syncthreads();
        uint32_t afr[4][4], bfr[4][2];
        #pragma unroll
        for (int mi = 0; mi < 4; mi++)
            ldsm4t(afr[mi][0], afr[mi][1], afr[mi][2], afr[mi][3],
                   smX + aRowOff + (wm + mi * 16) * 2);
        #pragma unroll
        for (int np = 0; np < 2; np++)
            ldsm4t(bfr[2 * np][0], bfr[2 * np][1], bfr[2 * np + 1][0], bfr[2 * np + 1][1],
                   smB + bRowOff + (wn + np * 16) * 2);
        #pragma unroll
        for (int mi = 0; mi < 4; mi++)
            #pragma unroll
            for (int ni = 0; ni < 4; ni++)
                mma_fp16(acc[mi][ni], afr[mi], bfr[ni]);
        __syncthreads();
    }

    __half* sout = g_states_h + (size_t)z * HP * NS;
    const int g = lane >> 2, tt = lane & 3;
    #pragma unroll
    for (int mi = 0; mi < 4; mi++)
        #pragma unroll
        for (int ni = 0; ni < 4; ni++) {
            int row = wm + mi * 16 + g;
            int col = wn + ni * 8 + 2 * tt;
            *(__half2*)(sout + (size_t)row * NS + col) =
                __floats2half2_rn(acc[mi][ni][0], acc[mi][ni][1]);
            *(__half2*)(sout + (size_t)(row + 8) * NS + col) =
                __floats2half2_rn(acc[mi][ni][2], acc[mi][ni][3]);
        }
}

// ---------------- sequential scan over chunks (half2, element-parallel) ----------------
__global__ void chunk_scan()
{
    const int bh = blockIdx.x;
    const int b = bh / NH, h = bh % NH;
    __shared__ float dec[NC];
    if (threadIdx.x < NC)
        dec[threadIdx.x] = __expf(g_Acs[((size_t)(b * NH + h) * NC + threadIdx.x) * CS + CS - 1]);
    __syncthreads();
    const int idx = (blockIdx.y * 256 + threadIdx.x) * 2;
    float2 carry = make_float2(0.f, 0.f);
    #pragma unroll
    for (int c = 0; c < NC; c++) {
        size_t base = ((size_t)((b * NC + c) * NH + h)) * HP * NS + idx;
        *(__half2*)(g_prev_h + base) = __floats2half2_rn(carry.x, carry.y);
        float2 s = __half22float2(*(const __half2*)(g_states_h + base));
        carry.x = carry.x * dec[c] + s.x;
        carry.y = carry.y * dec[c] + s.y;
    }
}

// ---------------- Y (fp16 MMA, 256 threads) ----------------
#define RM_STRIDE 48    // bytes per row (16 halves + 8 pad)
__global__ __launch_bounds__(256, 2) void y_fp16(const float* __restrict__ Dp)
{
    const int z = blockIdx.y;
    const int h = z % NH;
    const int bc = z / NH;
    const int c = bc % NC;
    const int b = bc / NC;
    const int m0 = blockIdx.x * 128;

    __shared__ float sAcs[CS], sdt[CS];
    __shared__ float sh_e[16];
    __shared__ __half As[128][24];
    __shared__ __half Bt[16][136];
    __shared__ __half B2[128][24];
    const int t = threadIdx.x;
    {
        const float* acs = g_Acs + ((size_t)(b * NH + h) * NC + c) * CS;
        sAcs[t] = acs[t];
        sdt[t] = g_dt[((size_t)b * LL + c * CS + t) * NH + h];
    }
    __syncthreads();

    const int lane = t & 31, w = t >> 5;
    const int wm = (w & 1) * 64, wn = (w >> 1) * 32;
    const int arow = t >> 1, ac8 = (t & 1) * 8;
    const int l_loc = m0 + arow;
    const float acs_l = sAcs[l_loc];
    const __half2 eAl2 = __float2half2_rn(__expf(acs_l));
    const int xr16 = t >> 4, xc8 = (t & 15) * 8;

    const uint32_t smA  = (uint32_t)__cvta_generic_to_shared(&As[0][0]);
    const uint32_t smBt = (uint32_t)__cvta_generic_to_shared(&Bt[0][0]);
    const uint32_t smB2 = (uint32_t)__cvta_generic_to_shared(&B2[0][0]);
    const uint32_t aFrag  = (uint32_t)((wm + (lane & 15)) * RM_STRIDE + (lane >> 4) * 16);
    const uint32_t btFrag = (uint32_t)(((lane & 7) + ((lane >> 3) & 1) * 8) * KM_STRIDE
                                       + ((lane >> 4) << 4));
    const uint32_t b2Frag = (uint32_t)((wn + ((lane >> 4) << 3) + (lane & 7)) * RM_STRIDE
                                       + ((lane >> 3) & 1) * 16);

    float acc[4][4][4];
    #pragma unroll
    for (int i = 0; i < 4; i++)
        #pragma unroll
        for (int j = 0; j < 4; j++)
            #pragma unroll
            for (int q = 0; q < 4; q++) acc[i][j][q] = 0.f;

    const float* cbt_l = g_CBT + (size_t)bc * CS * CS + (size_t)l_loc * CS;
    const __half* xrow = g_xc_h + ((size_t)b * LL + c * CS) * CONVD + h * HP;

    // ---- phase 1: intra-chunk, K = m0+128 (factorized decay exp) ----
    const int K1 = m0 + 128;
    for (int k0 = 0; k0 < K1; k0 += 16) {
        if (t < 16)
            sh_e[t] = __expf(sAcs[k0 + 15] - sAcs[k0 + t]) * sdt[k0 + t];
        __syncthreads();
        const float e_row = (l_loc >= k0) ? __expf(acs_l - sAcs[k0 + 15]) : 0.f;
        #pragma unroll
        for (int j = 0; j < 8; j += 2) {
            int s = k0 + ac8 + j;
            float v0 = (s     <= l_loc) ? cbt_l[s]     * e_row * sh_e[ac8 + j]     : 0.f;
            float v1 = (s + 1 <= l_loc) ? cbt_l[s + 1] * e_row * sh_e[ac8 + j + 1] : 0.f;
            *(__half2*)&As[arow][ac8 + j] = __floats2half2_rn(v0, v1);
        }
        const __half* xr = xrow + (size_t)(k0 + xr16) * CONVD + xc8;
        *(uint4*)&Bt[xr16][xc8] = *(const uint4*)(xr);
        __syncthreads();
        uint32_t afr[4][4], bfr[4][2];
        #pragma unroll
        for (int mi = 0; mi < 4; mi++)
            ldsm4(afr[mi][0], afr[mi][1], afr[mi][2], afr[mi][3],
                  smA + aFrag + mi * (16 * RM_STRIDE));
        #pragma unroll
        for (int np = 0; np < 2; np++)
            ldsm4t(bfr[2 * np][0], bfr[2 * np][1], bfr[2 * np + 1][0], bfr[2 * np + 1][1],
                   smBt + btFrag + (wn + np * 16) * 2);
        #pragma unroll
        for (int mi = 0; mi < 4; mi++)
            #pragma unroll
            for (int ni = 0; ni < 4; ni++)
                mma_fp16(acc[mi][ni], afr[mi], bfr[ni]);
        __syncthreads();
    }

    // ---- phase 2: inter-chunk, K = NS = 128 ----
    const __half* crow = g_xc_h + ((size_t)b * LL + c * CS) * CONVD + DINNER + NS;
    const __half* prow = g_prev_h + (size_t)z * HP * NS;
    for (int k0 = 0; k0 < NS; k0 += 16) {
        const __half* cr = crow + (size_t)l_loc * CONVD + k0 + ac8;
        uint4 cv = *(const uint4*)(cr);
        __half2* cp = (__half2*)&cv;
        #pragma unroll
        for (int q = 0; q < 4; q++) cp[q] = __hmul2(cp[q], eAl2);
        *(uint4*)&As[arow][ac8] = cv;
        const __half* pr = prow + (size_t)arow * NS + k0 + ac8;
        *(uint4*)&B2[arow][ac8] = *(const uint4*)(pr);
        __syncthreads();
        uint32_t afr[4][4], bfr[4][2];
        #pragma unroll
        for (int mi = 0; mi < 4; mi++)
            ldsm4(afr[mi][0], afr[mi][1], afr[mi][2], afr[mi][3],
                  smA + aFrag + mi * (16 * RM_STRIDE));
        #pragma unroll
        for (int np = 0; np < 2; np++)
            ldsm4(bfr[2 * np][0], bfr[2 * np][1], bfr[2 * np + 1][0], bfr[2 * np + 1][1],
                  smB2 + b2Frag + np * (16 * RM_STRIDE));
        #pragma unroll
        for (int mi = 0; mi < 4; mi++)
            #pragma unroll
            for (int ni = 0; ni < 4; ni++)
                mma_fp16(acc[mi][ni], afr[mi], bfr[ni]);
        __syncthreads();
    }

    const float Dh = Dp[h];
    const int g = lane >> 2, tt = lane & 3;
    #pragma unroll
    for (int mi = 0; mi < 4; mi++)
        #pragma unroll
        for (int ni = 0; ni < 4; ni++) {
            int l0 = m0 + wm + mi * 16 + g;
            int p = wn + ni * 8 + 2 * tt;
            float2 xv0 = __half22float2(*(const __half2*)(xrow + (size_t)l0 * CONVD + p));
            float2 xv1 = __half22float2(*(const __half2*)(xrow + (size_t)(l0 + 8) * CONVD + p));
            __half* o0 = g_y_h + ((size_t)b * LL + c * CS + l0) * DINNER + h * HP + p;
            __half* o1 = g_y_h + ((size_t)b * LL + c * CS + l0 + 8) * DINNER + h * HP + p;
            *(__half2*)o0 = __floats2half2_rn(acc[mi][ni][0] + Dh * xv0.x,
                                              acc[mi][ni][1] + Dh * xv0.y);
            *(__half2*)o1 = __floats2half2_rn(acc[mi][ni][2] + Dh * xv1.x,
                                              acc[mi][ni][3] + Dh * xv1.y);
        }
}

// ---------------- gating (silu(z)) + RMS norm -> fp16 ----------------
__global__ void gate_norm(const float* __restrict__ norm_w)
{
    const int row = blockIdx.x;
    const int t = threadIdx.x;
    __shared__ float red[256];
    float vals[8];
    float local = 0.f;
    const __half* yrow = g_y_h + (size_t)row * DINNER;
    const __half* zrow = g_zx_h + (size_t)row * DIP;
    #pragma unroll
    for (int e = 0; e < 8; e++) {
        int i = e * 256 + t;
        float zv = __half2float(zrow[i]);
        float gv = __half2float(yrow[i]) * zv / (1.f + __expf(-zv));
        vals[e] = gv;
        local += gv * gv;
    }
    red[t] = local;
    __syncthreads();
    for (int off = 128; off > 0; off >>= 1) {
        if (t < off) red[t] += red[t + off];
        __syncthreads();
    }
    float scale = rsqrtf(red[0] / (float)DINNER + 1e-5f);
    __half* out = g_yg_h + (size_t)row * DINNER;
    #pragma unroll
    for (int e = 0; e < 8; e++) {
        int i = e * 256 + t;
        out[i] = __float2half(vals[e] * scale * norm_w[i]);
    }
}

// ---------------- host launcher ----------------
extern "C" void kernel_launch(void* const* d_in, const int* in_sizes, int n_in,
                              void* d_out, int out_size)
{
    const float* u       = (const float*)d_in[0];
    const float* W_in    = (const float*)d_in[1];
    const float* conv_w  = (const float*)d_in[2];
    const float* conv_b  = (const float*)d_in[3];
    const float* dt_bias = (const float*)d_in[4];
    const float* A_log   = (const float*)d_in[5];
    const float* Dp      = (const float*)d_in[6];
    const float* norm_w  = (const float*)d_in[7];
    const float* W_out   = (const float*)d_in[8];
    float* out = (float*)d_out;

    float* cbt;
    __half *zxh, *uh, *wih, *woh, *xch, *ygh;
    cudaGetSymbolAddress((void**)&cbt, g_CBT);
    cudaGetSymbolAddress((void**)&zxh, g_zx_h);
    cudaGetSymbolAddress((void**)&uh,  g_u_h);
    cudaGetSymbolAddress((void**)&wih, g_Win_h);
    cudaGetSymbolAddress((void**)&woh, g_Wout_h);
    cudaGetSymbolAddress((void**)&xch, g_xc_h);
    cudaGetSymbolAddress((void**)&ygh, g_yg_h);

    const int gemmSmem = GSTG * (A_STG_B + B_STG_B);  // 92160 B
    cudaFuncSetAttribute(gemm_fp16_nt,
                         cudaFuncAttributeMaxDynamicSharedMemorySize, gemmSmem);

    // 0) convert dense-GEMM inputs to fp16
    {
        int nu = BB * LL * DM;
        round_fp16<<<(nu / 4 + 255) / 256, 256>>>(u, uh, nu);
        int nwi = DIP * DM;
        round_fp16<<<(nwi / 4 + 255) / 256, 256>>>(W_in, wih, nwi);
        int nwo = DM * DINNER;
        round_fp16<<<(nwo / 4 + 255) / 256, 256>>>(W_out, woh, nwo);
    }

    // 1) in-proj (fp16 MMA, fp16 output)
    gemm_fp16_nt<<<dim3((DIP + 127) / 128, (BB * LL) / 256, 1), 256, gemmSmem>>>(
        uh, DM, 0, wih, DM, 0, zxh, DIP, 0, DIP, DM, 1);

    // 2) conv + silu + dt softplus (fp16 in/out)
    conv_silu_dt<<<dim3(CONVD / 256, BB * LL), 256>>>(conv_w, conv_b, dt_bias);

    // 3) per-chunk cumsum of dA
    chunk_cumsum<<<BB * NH * NC, CS>>>(A_log);

    // 4) CBT[b,c] = C @ B^T (fp16 MMA, fp32 output)
    gemm_fp16_nt<<<dim3(2, 1, BB * NC), 256, gemmSmem>>>(
        xch + DINNER + NS, CONVD, (long long)CS * CONVD,
        xch + DINNER,      CONVD, (long long)CS * CONVD,
        cbt, CS, (long long)CS * CS,
        CS, NS, 0);

    // 5) per-chunk states (fp16 MMA)
    states_fp16<<<BB * NC * NH, 256>>>();

    // 6) inter-chunk scan (half2)
    chunk_scan<<<dim3(BB * NH, (HP * NS) / 512), 256>>>();

    // 7) Y = diag + off + D*x (fp16 MMA, fp16 output)
    y_fp16<<<dim3(2, BB * NC * NH), 256>>>(Dp);

    // 8) gating + RMS norm (fp16 in/out)
    gate_norm<<<BB * LL, 256>>>(norm_w);

    // 9) out-proj (fp16 MMA, fp32 output)
    gemm_fp16_nt<<<dim3(DM / 128, (BB * LL) / 256, 1), 256, gemmSmem>>>(
        ygh, DINNER, 0, woh, DINNER, 0, out, DM, 0, DM, DINNER, 0);
}